// round 7
// baseline (speedup 1.0000x reference)
#include <cuda_runtime.h>
#include <cuda_fp16.h>
#include <cstdint>
#include <cstddef>

// ---------------------------------------------------------------------------
// Dims
// ---------------------------------------------------------------------------
constexpr int    T_STEPS = 64;
constexpr int    BATCH   = 1024;
constexpr int    HID     = 512;
constexpr int    G3      = 3 * HID;                  // 1536
constexpr size_t NROWS   = (size_t)T_STEPS * BATCH;  // 65536
constexpr int    KDIM    = 512;

// ---------------------------------------------------------------------------
// PTX helpers (arch-unconditional, sm_80-era)
// ---------------------------------------------------------------------------
__device__ __forceinline__ uint32_t smem_u32(const void* p) {
    uint32_t a;
    asm("{ .reg .u64 t; cvta.to.shared.u64 t, %1; cvt.u32.u64 %0, t; }"
        : "=r"(a) : "l"(p));
    return a;
}
#define CP16(s, g) \
    asm volatile("cp.async.cg.shared.global [%0], [%1], 16;\n" :: "r"(s), "l"(g) : "memory")
#define CP_COMMIT() asm volatile("cp.async.commit_group;\n" ::: "memory")
#define CP_WAIT_N(n) asm volatile("cp.async.wait_group %0;" :: "n"(n) : "memory")

#define LDM_X4(r, addr)                                                         \
    asm volatile("ldmatrix.sync.aligned.m8n8.x4.shared.b16 {%0,%1,%2,%3}, [%4];" \
        : "=r"((r)[0]), "=r"((r)[1]), "=r"((r)[2]), "=r"((r)[3]) : "r"(addr))

#define MMA_F16(d, a, b0, b1)                                                   \
    asm volatile("mma.sync.aligned.m16n8k16.row.col.f32.f16.f16.f32 "           \
        "{%0,%1,%2,%3}, {%4,%5,%6,%7}, {%8,%9}, {%0,%1,%2,%3};"                 \
        : "+f"((d)[0]), "+f"((d)[1]), "+f"((d)[2]), "+f"((d)[3])                \
        : "r"((a)[0]), "r"((a)[1]), "r"((a)[2]), "r"((a)[3]), "r"(b0), "r"(b1))

// ---------------------------------------------------------------------------
// Scratch
// ---------------------------------------------------------------------------
__device__ float g_h   [NROWS * HID];     // fp32 ODE state
__device__ float g_acc [NROWS * HID];     // RK4 accumulator
__device__ float g_z   [NROWS * HID];     // fp32 GEMM out (pre-LN)
__device__ float g_gi  [NROWS * G3];
__device__ float g_beff[16 * HID];        // all 16 time-folded W1 biases

__device__ __half g_hhi[NROWS * HID], g_hlo[NROWS * HID];  // h state split
__device__ __half g_xhi[NROWS * HID];                      // LN outputs (hi only)
__device__ __half g_yhi[NROWS * HID];                      // RK4 Y output (hi only)
__device__ __half g_s0hi[BATCH * HID], g_s0lo[BATCH * HID]; // GRU state ping
__device__ __half g_s1hi[BATCH * HID], g_s1lo[BATCH * HID]; // GRU state pong
__device__ __half g_w1hi[HID * HID],  g_w1lo[HID * HID];
__device__ __half g_w2hi[HID * HID],  g_w2lo[HID * HID];
__device__ __half g_wohi[HID * HID],  g_wolo[HID * HID];
__device__ __half g_wihi[G3 * HID],   g_wilo[G3 * HID];
__device__ __half g_whhi[G3 * HID],   g_whlo[G3 * HID];

// ---------------------------------------------------------------------------
// fp16 split helpers
// ---------------------------------------------------------------------------
__device__ __forceinline__ void split1h(float v, __half& hi, __half& lo) {
    hi = __float2half(v);
    lo = __float2half(v - __half2float(hi));
}
__device__ __forceinline__ void split_store_pair(__half* Hi, __half* Lo,
                                                 size_t i, float a, float b) {
    __half2 h, l;
    split1h(a, h.x, l.x); split1h(b, h.y, l.y);
    *reinterpret_cast<__half2*>(Hi + i) = h;
    *reinterpret_cast<__half2*>(Lo + i) = l;
}

// ===========================================================================
// fp16 split GEMM (generic): C[M,N] = A @ B^T + bias, B pre-transposed [N,512].
// PRODUCTS==2: C = Ah*(Bh+Bl).  PRODUCTS==3: + Al*Bh.
// BM x 128 tile, BK=32, 16 chunks, 256 threads (8 warps 2Mx4N).
// ===========================================================================
template<int BM, int PRODUCTS>
__global__ void __launch_bounds__(256, PRODUCTS == 2 ? 2 : 1)
gemm_f16(const __half* __restrict__ Ahi, const __half* __restrict__ Alo,
         const __half* __restrict__ Bhi, const __half* __restrict__ Blo,
         const float* __restrict__ bias, float* __restrict__ C, int N)
{
    constexpr int MF    = BM / 32;
    constexpr int AB    = BM * 64;
    constexpr int ASETS = (PRODUCTS == 3) ? 2 : 1;
    constexpr int STB   = ASETS * AB + 16384;
    constexpr int S     = (PRODUCTS == 2) ? 4 : 3;

    extern __shared__ char smem[];
    const uint32_t sb = smem_u32(smem);
    const int tid  = threadIdx.x;
    const int lane = tid & 31;
    const int wid  = tid >> 5;
    const int wm   = (wid >> 2) * (BM / 2);
    const int wn   = (wid & 3) * 32;
    const size_t bm = (size_t)blockIdx.y * BM;
    const size_t bn = (size_t)blockIdx.x * 128;

    float acc[MF][4][4];
    #pragma unroll
    for (int i = 0; i < MF; i++)
        #pragma unroll
        for (int j = 0; j < 4; j++)
            #pragma unroll
            for (int v = 0; v < 4; v++) acc[i][j][v] = 0.f;

    auto g2s = [&](int kc) {
        const uint32_t st = sb + (uint32_t)(kc % S) * STB;
        const int ko = kc * 32;
        const int c  = tid & 3;
        const int r0 = tid >> 2;
        #pragma unroll
        for (int i = 0; i < BM / 64; i++) {
            const int r = r0 + i * 64;
            const uint32_t sw = (uint32_t)(r * 64 + 16 * (c ^ ((r >> 1) & 3)));
            CP16(st + sw, Ahi + (bm + r) * KDIM + ko + c * 8);
            if constexpr (PRODUCTS == 3)
                CP16(st + AB + sw, Alo + (bm + r) * KDIM + ko + c * 8);
        }
        #pragma unroll
        for (int i = 0; i < 2; i++) {
            const int r = r0 + i * 64;
            const uint32_t sw = (uint32_t)(r * 64 + 16 * (c ^ ((r >> 1) & 3)));
            CP16(st + ASETS * AB + sw,        Bhi + (bn + r) * KDIM + ko + c * 8);
            CP16(st + ASETS * AB + 8192 + sw, Blo + (bn + r) * KDIM + ko + c * 8);
        }
        CP_COMMIT();
    };

    #pragma unroll
    for (int kc = 0; kc < S - 1; kc++) g2s(kc);

    #pragma unroll 1
    for (int kc = 0; kc < 16; kc++) {
        if constexpr (S == 4) {
            if (kc <= 13) CP_WAIT_N(2);
            else if (kc == 14) CP_WAIT_N(1);
            else CP_WAIT_N(0);
        } else {
            if (kc <= 14) CP_WAIT_N(1);
            else CP_WAIT_N(0);
        }
        __syncthreads();
        if (kc + S - 1 < 16) g2s(kc + S - 1);
        const uint32_t st = sb + (uint32_t)(kc % S) * STB;

        #pragma unroll
        for (int s = 0; s < 2; s++) {
            uint32_t ah[MF][4], al[MF][4], bh[2][4], bl[2][4];
            #pragma unroll
            for (int mf = 0; mf < MF; mf++) {
                const int ar = wm + mf * 16 + (lane & 15);
                const int ac = s * 2 + (lane >> 4);
                const uint32_t sw = (uint32_t)(ar * 64 + 16 * (ac ^ ((ar >> 1) & 3)));
                LDM_X4(ah[mf], st + sw);
                if constexpr (PRODUCTS == 3) LDM_X4(al[mf], st + AB + sw);
            }
            #pragma unroll
            for (int nf16 = 0; nf16 < 2; nf16++) {
                const int br = wn + nf16 * 16 + (lane & 7) + ((lane >> 4) & 1) * 8;
                const int bc = s * 2 + ((lane >> 3) & 1);
                const uint32_t sw = (uint32_t)(br * 64 + 16 * (bc ^ ((br >> 1) & 3)));
                LDM_X4(bh[nf16], st + ASETS * AB + sw);
                LDM_X4(bl[nf16], st + ASETS * AB + 8192 + sw);
            }
            #pragma unroll
            for (int mf = 0; mf < MF; mf++)
                #pragma unroll
                for (int nf = 0; nf < 4; nf++) {
                    const uint32_t b0h = bh[nf >> 1][(nf & 1) * 2];
                    const uint32_t b1h = bh[nf >> 1][(nf & 1) * 2 + 1];
                    const uint32_t b0l = bl[nf >> 1][(nf & 1) * 2];
                    const uint32_t b1l = bl[nf >> 1][(nf & 1) * 2 + 1];
                    MMA_F16(acc[mf][nf], ah[mf], b0h, b1h);
                    MMA_F16(acc[mf][nf], ah[mf], b0l, b1l);
                    if constexpr (PRODUCTS == 3)
                        MMA_F16(acc[mf][nf], al[mf], b0h, b1h);
                }
        }
    }

    #pragma unroll
    for (int mf = 0; mf < MF; mf++) {
        const size_t r0 = bm + wm + mf * 16 + (lane >> 2);
        #pragma unroll
        for (int nf = 0; nf < 4; nf++) {
            const int col = wn + nf * 8 + (lane & 3) * 2;
            const float b0 = bias[bn + col], b1 = bias[bn + col + 1];
            *reinterpret_cast<float2*>(C + r0 * N + bn + col) =
                make_float2(acc[mf][nf][0] + b0, acc[mf][nf][1] + b1);
            *reinterpret_cast<float2*>(C + (r0 + 8) * N + bn + col) =
                make_float2(acc[mf][nf][2] + b0, acc[mf][nf][3] + b1);
        }
    }
}

constexpr int SMEM_P2_128 = 4 * (1 * 128 * 64 + 16384);   // 98304
constexpr int SMEM_P3_128 = 3 * (2 * 128 * 64 + 16384);   // 98304

// ===========================================================================
// Wout GEMM (P2, BM=128, N=512) + RK4 epilogue.
// mode0: Acc=K, Y=H+wy*K -> Yhi.  mode1: Acc+=wacc*K, Y -> Yhi.
// mode2: H+=(Acc+K)/24 -> H fp32, Yhi=hi(H), Hlo2=lo(H).
// ===========================================================================
__global__ void __launch_bounds__(256, 2)
gemm_rk4(const __half* __restrict__ Ahi,
         const __half* __restrict__ Bhi, const __half* __restrict__ Blo,
         const float* __restrict__ bias,
         float* __restrict__ H, float* __restrict__ Acc,
         __half* __restrict__ Yhi, __half* __restrict__ Hlo2,
         float wacc, float wy, int mode)
{
    constexpr int AB  = 128 * 64;
    constexpr int STB = AB + 16384;     // 24576
    extern __shared__ char smem[];
    const uint32_t sb = smem_u32(smem);
    const int tid  = threadIdx.x;
    const int lane = tid & 31;
    const int wid  = tid >> 5;
    const int wm   = (wid >> 2) * 64;
    const int wn   = (wid & 3) * 32;
    const size_t bm = (size_t)blockIdx.y * 128;
    const size_t bn = (size_t)blockIdx.x * 128;

    float acc[4][4][4];
    #pragma unroll
    for (int i = 0; i < 4; i++)
        #pragma unroll
        for (int j = 0; j < 4; j++)
            #pragma unroll
            for (int v = 0; v < 4; v++) acc[i][j][v] = 0.f;

    auto g2s = [&](int kc) {
        const uint32_t st = sb + (uint32_t)(kc & 3) * STB;
        const int ko = kc * 32;
        const int c  = tid & 3;
        const int r0 = tid >> 2;
        #pragma unroll
        for (int i = 0; i < 2; i++) {
            const int r = r0 + i * 64;
            const uint32_t sw = (uint32_t)(r * 64 + 16 * (c ^ ((r >> 1) & 3)));
            CP16(st + sw,              Ahi + (bm + r) * KDIM + ko + c * 8);
            CP16(st + AB + sw,         Bhi + (bn + r) * KDIM + ko + c * 8);
            CP16(st + AB + 8192 + sw,  Blo + (bn + r) * KDIM + ko + c * 8);
        }
        CP_COMMIT();
    };

    #pragma unroll
    for (int kc = 0; kc < 3; kc++) g2s(kc);

    #pragma unroll 1
    for (int kc = 0; kc < 16; kc++) {
        if (kc <= 13) CP_WAIT_N(2);
        else if (kc == 14) CP_WAIT_N(1);
        else CP_WAIT_N(0);
        __syncthreads();
        if (kc + 3 < 16) g2s(kc + 3);
        const uint32_t st = sb + (uint32_t)(kc & 3) * STB;

        #pragma unroll
        for (int s = 0; s < 2; s++) {
            uint32_t ah[4][4], bh[2][4], bl[2][4];
            #pragma unroll
            for (int mf = 0; mf < 4; mf++) {
                const int ar = wm + mf * 16 + (lane & 15);
                const int ac = s * 2 + (lane >> 4);
                LDM_X4(ah[mf], st + (uint32_t)(ar * 64 + 16 * (ac ^ ((ar >> 1) & 3))));
            }
            #pragma unroll
            for (int nf16 = 0; nf16 < 2; nf16++) {
                const int br = wn + nf16 * 16 + (lane & 7) + ((lane >> 4) & 1) * 8;
                const int bc = s * 2 + ((lane >> 3) & 1);
                const uint32_t sw = (uint32_t)(br * 64 + 16 * (bc ^ ((br >> 1) & 3)));
                LDM_X4(bh[nf16], st + AB + sw);
                LDM_X4(bl[nf16], st + AB + 8192 + sw);
            }
            #pragma unroll
            for (int mf = 0; mf < 4; mf++)
                #pragma unroll
                for (int nf = 0; nf < 4; nf++) {
                    MMA_F16(acc[mf][nf], ah[mf],
                            bh[nf >> 1][(nf & 1) * 2], bh[nf >> 1][(nf & 1) * 2 + 1]);
                    MMA_F16(acc[mf][nf], ah[mf],
                            bl[nf >> 1][(nf & 1) * 2], bl[nf >> 1][(nf & 1) * 2 + 1]);
                }
        }
    }

    // RK4 epilogue
    #pragma unroll
    for (int mf = 0; mf < 4; mf++)
        #pragma unroll
        for (int nf = 0; nf < 4; nf++) {
            const int col = wn + nf * 8 + 2 * (lane & 3);
            const float b0 = bias[bn + col], b1 = bias[bn + col + 1];
            #pragma unroll
            for (int hv = 0; hv < 2; hv++) {
                const size_t row = bm + wm + mf * 16 + (lane >> 2) + 8 * hv;
                const size_t ix = row * 512 + bn + col;
                const float k0 = acc[mf][nf][2 * hv]     + b0;
                const float k1 = acc[mf][nf][2 * hv + 1] + b1;
                if (mode == 0) {
                    *reinterpret_cast<float2*>(Acc + ix) = make_float2(k0, k1);
                    const float2 h2 = *reinterpret_cast<const float2*>(H + ix);
                    __half2 y;
                    y.x = __float2half(fmaf(wy, k0, h2.x));
                    y.y = __float2half(fmaf(wy, k1, h2.y));
                    *reinterpret_cast<__half2*>(Yhi + ix) = y;
                } else if (mode == 1) {
                    float2 a2 = *reinterpret_cast<const float2*>(Acc + ix);
                    a2.x = fmaf(wacc, k0, a2.x); a2.y = fmaf(wacc, k1, a2.y);
                    *reinterpret_cast<float2*>(Acc + ix) = a2;
                    const float2 h2 = *reinterpret_cast<const float2*>(H + ix);
                    __half2 y;
                    y.x = __float2half(fmaf(wy, k0, h2.x));
                    y.y = __float2half(fmaf(wy, k1, h2.y));
                    *reinterpret_cast<__half2*>(Yhi + ix) = y;
                } else {
                    const float2 a2 = *reinterpret_cast<const float2*>(Acc + ix);
                    float2 h2 = *reinterpret_cast<const float2*>(H + ix);
                    const float cc = 1.0f / 24.0f;
                    h2.x = fmaf(a2.x + k0, cc, h2.x);
                    h2.y = fmaf(a2.y + k1, cc, h2.y);
                    *reinterpret_cast<float2*>(H + ix) = h2;
                    split_store_pair(Yhi, Hlo2, ix, h2.x, h2.y);
                }
            }
        }
}

// ===========================================================================
// Fused GRU step: gh = h @ W_hh^T (3 gates, P3) + GRU nonlinearity epilogue.
// BM=32 batch rows x 128 units x 3 gates; 256 threads; 3 stages.
// grid = (512/128, 1024/32) = (4, 32).
// ===========================================================================
constexpr int GSTB     = 4096 + 3 * 16384;     // A(hi+lo) 4KB + 3 gates x (hi 8K + lo 8K)
constexpr int GRU_SMEM = 3 * GSTB;             // 159744

__global__ void __launch_bounds__(256, 1)
gru_fused(const __half* __restrict__ Shi, const __half* __restrict__ Slo,
          const __half* __restrict__ Whh, const __half* __restrict__ Whl,
          const float* __restrict__ bhh, const float* __restrict__ GI,
          __half* __restrict__ OShi, __half* __restrict__ OSlo)
{
    extern __shared__ char smem[];
    const uint32_t sb = smem_u32(smem);
    const int tid  = threadIdx.x;
    const int lane = tid & 31;
    const int wid  = tid >> 5;
    const int wm   = (wid >> 2) * 16;
    const int wn   = (wid & 3) * 32;
    const size_t bm = (size_t)blockIdx.y * 32;
    const int c0 = blockIdx.x * 128;

    float acc[3][4][4];
    #pragma unroll
    for (int g = 0; g < 3; g++)
        #pragma unroll
        for (int j = 0; j < 4; j++)
            #pragma unroll
            for (int v = 0; v < 4; v++) acc[g][j][v] = 0.f;

    auto g2s = [&](int kc) {
        const uint32_t st = sb + (uint32_t)(kc % 3) * GSTB;
        const int ko = kc * 32;
        const int c  = tid & 3;
        const int r0 = tid >> 2;                     // 0..63
        if (r0 < 32) {
            const uint32_t sw = (uint32_t)(r0 * 64 + 16 * (c ^ ((r0 >> 1) & 3)));
            CP16(st + sw,        Shi + (bm + r0) * KDIM + ko + c * 8);
            CP16(st + 2048 + sw, Slo + (bm + r0) * KDIM + ko + c * 8);
        }
        #pragma unroll
        for (int g = 0; g < 3; g++) {
            const uint32_t gb = st + 4096 + (uint32_t)g * 16384;
            #pragma unroll
            for (int i = 0; i < 2; i++) {
                const int r = r0 + i * 64;
                const uint32_t sw = (uint32_t)(r * 64 + 16 * (c ^ ((r >> 1) & 3)));
                const size_t wr = (size_t)(g * 512 + c0 + r) * KDIM + ko + c * 8;
                CP16(gb + sw,        Whh + wr);
                CP16(gb + 8192 + sw, Whl + wr);
            }
        }
        CP_COMMIT();
    };

    g2s(0); g2s(1);

    #pragma unroll 1
    for (int kc = 0; kc < 16; kc++) {
        if (kc <= 14) CP_WAIT_N(1);
        else CP_WAIT_N(0);
        __syncthreads();
        if (kc + 2 < 16) g2s(kc + 2);
        const uint32_t st = sb + (uint32_t)(kc % 3) * GSTB;

        #pragma unroll
        for (int s = 0; s < 2; s++) {
            uint32_t ah[4], al[4];
            {
                const int ar = wm + (lane & 15);
                const int ac = s * 2 + (lane >> 4);
                const uint32_t sw = (uint32_t)(ar * 64 + 16 * (ac ^ ((ar >> 1) & 3)));
                LDM_X4(ah, st + sw);
                LDM_X4(al, st + 2048 + sw);
            }
            #pragma unroll
            for (int g = 0; g < 3; g++) {
                const uint32_t gb = st + 4096 + (uint32_t)g * 16384;
                uint32_t bh[2][4], bl[2][4];
                #pragma unroll
                for (int nf16 = 0; nf16 < 2; nf16++) {
                    const int br = wn + nf16 * 16 + (lane & 7) + ((lane >> 4) & 1) * 8;
                    const int bc = s * 2 + ((lane >> 3) & 1);
                    const uint32_t sw = (uint32_t)(br * 64 + 16 * (bc ^ ((br >> 1) & 3)));
                    LDM_X4(bh[nf16], gb + sw);
                    LDM_X4(bl[nf16], gb + 8192 + sw);
                }
                #pragma unroll
                for (int nf = 0; nf < 4; nf++) {
                    const uint32_t b0h = bh[nf >> 1][(nf & 1) * 2];
                    const uint32_t b1h = bh[nf >> 1][(nf & 1) * 2 + 1];
                    const uint32_t b0l = bl[nf >> 1][(nf & 1) * 2];
                    const uint32_t b1l = bl[nf >> 1][(nf & 1) * 2 + 1];
                    MMA_F16(acc[g][nf], ah, b0h, b1h);
                    MMA_F16(acc[g][nf], ah, b0l, b1l);
                    MMA_F16(acc[g][nf], al, b0h, b1h);
                }
            }
        }
    }

    // GRU epilogue (torch gate order r,z,n)
    #pragma unroll
    for (int nf = 0; nf < 4; nf++) {
        const int col = wn + nf * 8 + 2 * (lane & 3);
        const int u = c0 + col;
        const float2 br = *reinterpret_cast<const float2*>(bhh + u);
        const float2 bz = *reinterpret_cast<const float2*>(bhh + 512 + u);
        const float2 bn_ = *reinterpret_cast<const float2*>(bhh + 1024 + u);
        #pragma unroll
        for (int hv = 0; hv < 2; hv++) {
            const size_t row = bm + wm + (lane >> 2) + 8 * hv;
            const float2 gir = *reinterpret_cast<const float2*>(GI + row * 1536 + u);
            const float2 giz = *reinterpret_cast<const float2*>(GI + row * 1536 + 512 + u);
            const float2 gin = *reinterpret_cast<const float2*>(GI + row * 1536 + 1024 + u);
            const size_t ix = row * 512 + u;
            const __half2 hp_h = *reinterpret_cast<const __half2*>(Shi + ix);
            const __half2 hp_l = *reinterpret_cast<const __half2*>(Slo + ix);
            const float hp0 = __half2float(hp_h.x) + __half2float(hp_l.x);
            const float hp1 = __half2float(hp_h.y) + __half2float(hp_l.y);
            const float r0g = 1.f / (1.f + expf(-(gir.x + acc[0][nf][2 * hv]     + br.x)));
            const float r1g = 1.f / (1.f + expf(-(gir.y + acc[0][nf][2 * hv + 1] + br.y)));
            const float z0g = 1.f / (1.f + expf(-(giz.x + acc[1][nf][2 * hv]     + bz.x)));
            const float z1g = 1.f / (1.f + expf(-(giz.y + acc[1][nf][2 * hv + 1] + bz.y)));
            const float n0g = tanhf(gin.x + r0g * (acc[2][nf][2 * hv]     + bn_.x));
            const float n1g = tanhf(gin.y + r1g * (acc[2][nf][2 * hv + 1] + bn_.y));
            const float h0 = (1.f - z0g) * n0g + z0g * hp0;
            const float h1 = (1.f - z1g) * n1g + z1g * hp1;
            split_store_pair(OShi, OSlo, ix, h0, h1);
        }
    }
}

// ---------------------------------------------------------------------------
// LayerNorm(512)+LeakyReLU, warp-per-row. fp32 in -> fp16 HI only.
// ---------------------------------------------------------------------------
__global__ void ln_lrelu(const float* __restrict__ Z,
                         const float* __restrict__ g, const float* __restrict__ b,
                         __half* __restrict__ Xhi)
{
    const int lane = threadIdx.x & 31;
    const size_t row = (size_t)blockIdx.x * 8 + (threadIdx.x >> 5);
    const float* z = Z + row * 512;

    float4 v[4];
    #pragma unroll
    for (int i = 0; i < 4; i++)
        v[i] = *reinterpret_cast<const float4*>(z + i * 128 + lane * 4);

    float s = 0.f;
    #pragma unroll
    for (int i = 0; i < 4; i++) s += v[i].x + v[i].y + v[i].z + v[i].w;
    #pragma unroll
    for (int o = 16; o > 0; o >>= 1) s += __shfl_xor_sync(0xffffffffu, s, o);
    const float mean = s * (1.0f / 512.0f);

    float q = 0.f;
    #pragma unroll
    for (int i = 0; i < 4; i++) {
        const float d0 = v[i].x - mean, d1 = v[i].y - mean;
        const float d2 = v[i].z - mean, d3 = v[i].w - mean;
        q += d0 * d0 + d1 * d1 + d2 * d2 + d3 * d3;
    }
    #pragma unroll
    for (int o = 16; o > 0; o >>= 1) q += __shfl_xor_sync(0xffffffffu, q, o);
    const float rstd = rsqrtf(q * (1.0f / 512.0f) + 1e-5f);

    #pragma unroll
    for (int i = 0; i < 4; i++) {
        const int c = i * 128 + lane * 4;
        const float4 gg = *reinterpret_cast<const float4*>(g + c);
        const float4 bb = *reinterpret_cast<const float4*>(b + c);
        float y0 = fmaf((v[i].x - mean) * rstd, gg.x, bb.x);
        float y1 = fmaf((v[i].y - mean) * rstd, gg.y, bb.y);
        float y2 = fmaf((v[i].z - mean) * rstd, gg.z, bb.z);
        float y3 = fmaf((v[i].w - mean) * rstd, gg.w, bb.w);
        y0 = (y0 > 0.f) ? y0 : 0.01f * y0;
        y1 = (y1 > 0.f) ? y1 : 0.01f * y1;
        y2 = (y2 > 0.f) ? y2 : 0.01f * y2;
        y3 = (y3 > 0.f) ? y3 : 0.01f * y3;
        __half2 p0; p0.x = __float2half(y0); p0.y = __float2half(y1);
        __half2 p1; p1.x = __float2half(y2); p1.y = __float2half(y3);
        *reinterpret_cast<__half2*>(Xhi + row * 512 + c)     = p0;
        *reinterpret_cast<__half2*>(Xhi + row * 512 + c + 2) = p1;
    }
}

// ---------------------------------------------------------------------------
// obs -> hidden: Linear(8->512)+LN+LeakyReLU; fp32 H + fp16 split
// ---------------------------------------------------------------------------
__device__ __forceinline__ float block_sum512(float x, float* red, int tid) {
    #pragma unroll
    for (int o = 16; o > 0; o >>= 1) x += __shfl_xor_sync(0xffffffffu, x, o);
    __syncthreads();
    if ((tid & 31) == 0) red[tid >> 5] = x;
    __syncthreads();
    float t = 0.f;
    #pragma unroll
    for (int i = 0; i < 8; i++) t += red[i];
    return t;
}

__global__ void obs_embed(const float* __restrict__ xs, const float* __restrict__ W,
                          const float* __restrict__ bias,
                          const float* __restrict__ lg, const float* __restrict__ lb,
                          float* __restrict__ H,
                          __half* __restrict__ Hhi, __half* __restrict__ Hlo)
{
    __shared__ float xv[8];
    __shared__ float red[8];
    const size_t row = blockIdx.x;
    const int tid = threadIdx.x;
    const int c = 2 * tid;
    if (tid < 8) xv[tid] = xs[row * 8 + tid];
    __syncthreads();
    float2 v = *reinterpret_cast<const float2*>(bias + c);
    #pragma unroll
    for (int k = 0; k < 8; k++) {
        float2 w = *reinterpret_cast<const float2*>(W + k * 512 + c);
        v.x = fmaf(xv[k], w.x, v.x);
        v.y = fmaf(xv[k], w.y, v.y);
    }
    const float mean = block_sum512(v.x + v.y, red, tid) * (1.f / 512.f);
    const float d0 = v.x - mean, d1 = v.y - mean;
    const float rstd = rsqrtf(block_sum512(d0 * d0 + d1 * d1, red, tid) * (1.f / 512.f) + 1e-5f);
    const float2 gg = *reinterpret_cast<const float2*>(lg + c);
    const float2 bb = *reinterpret_cast<const float2*>(lb + c);
    float y0 = fmaf(d0 * rstd, gg.x, bb.x);
    float y1 = fmaf(d1 * rstd, gg.y, bb.y);
    y0 = (y0 > 0.f) ? y0 : 0.01f * y0;
    y1 = (y1 > 0.f) ? y1 : 0.01f * y1;
    *reinterpret_cast<float2*>(H + row * 512 + c) = make_float2(y0, y1);
    split_store_pair(Hhi, Hlo, row * 512 + c, y0, y1);
}

// All 16 time-folded W1 biases at once: beff[(s*4+st)*512+n]
__global__ void make_bias_all(float* __restrict__ beff, const float* __restrict__ b1,
                              const float* __restrict__ w1_last)
{
    const int i = blockIdx.x * 256 + threadIdx.x;   // < 16*512
    const int idx = i >> 9;
    const int n = i & 511;
    const int s = idx >> 2, st = idx & 3;
    const float toff[4] = {0.f, 0.125f, 0.125f, 0.25f};
    const float tt = (float)s * 0.25f + toff[st];
    beff[i] = fmaf(tt, w1_last[n], b1[n]);
}

// W[K,N] (fp32 row-major) -> Whi/Wlo[N,K] fp16 split (transposed)
__global__ void wsplit(const float* __restrict__ W,
                       __half* __restrict__ Whi, __half* __restrict__ Wlo,
                       int K, int N)
{
    int idx = blockIdx.x * blockDim.x + threadIdx.x;
    if (idx >= K * N) return;
    int k = idx / N, n = idx % N;
    __half hi, lo;
    split1h(W[idx], hi, lo);
    Whi[(size_t)n * K + k] = hi;
    Wlo[(size_t)n * K + k] = lo;
}

__global__ void zero_state(__half* __restrict__ hi, __half* __restrict__ lo)
{
    int i = blockIdx.x * blockDim.x + threadIdx.x;
    hi[i] = __float2half(0.f);
    lo[i] = __float2half(0.f);
}

__global__ void copy_out(float* __restrict__ dst,
                         const __half* __restrict__ hi, const __half* __restrict__ lo)
{
    int i = blockIdx.x * blockDim.x + threadIdx.x;
    dst[i] = __half2float(hi[i]) + __half2float(lo[i]);
}

// ---------------------------------------------------------------------------
// Launch
// ---------------------------------------------------------------------------
extern "C" void kernel_launch(void* const* d_in, const int* in_sizes, int n_in,
                              void* d_out, int out_size)
{
    const float* xs       = (const float*)d_in[0];
    const float* obs_W    = (const float*)d_in[1];
    const float* obs_b    = (const float*)d_in[2];
    const float* obs_lg   = (const float*)d_in[3];
    const float* obs_lb   = (const float*)d_in[4];
    const float* ode_W1   = (const float*)d_in[5];   // [513, 512]
    const float* ode_b1   = (const float*)d_in[6];
    const float* ln1_g    = (const float*)d_in[7];
    const float* ln1_b    = (const float*)d_in[8];
    const float* ode_W2   = (const float*)d_in[9];
    const float* ode_b2   = (const float*)d_in[10];
    const float* ln2_g    = (const float*)d_in[11];
    const float* ln2_b    = (const float*)d_in[12];
    const float* ode_Wout = (const float*)d_in[13];
    const float* ode_bout = (const float*)d_in[14];
    const float* W_ih     = (const float*)d_in[15];  // [512, 1536]
    const float* b_ih     = (const float*)d_in[16];
    const float* W_hh     = (const float*)d_in[17];
    const float* b_hh     = (const float*)d_in[18];

    float *p_h, *p_acc, *p_z, *p_gi, *p_beff;
    __half *p_hhi, *p_hlo, *p_xhi, *p_yhi, *s0h, *s0l, *s1h, *s1l;
    __half *w1h, *w1l, *w2h, *w2l, *woh, *wol, *wih, *wil, *whh, *whl;
    cudaGetSymbolAddress((void**)&p_h,    g_h);
    cudaGetSymbolAddress((void**)&p_acc,  g_acc);
    cudaGetSymbolAddress((void**)&p_z,    g_z);
    cudaGetSymbolAddress((void**)&p_gi,   g_gi);
    cudaGetSymbolAddress((void**)&p_beff, g_beff);
    cudaGetSymbolAddress((void**)&p_hhi,  g_hhi);
    cudaGetSymbolAddress((void**)&p_hlo,  g_hlo);
    cudaGetSymbolAddress((void**)&p_xhi,  g_xhi);
    cudaGetSymbolAddress((void**)&p_yhi,  g_yhi);
    cudaGetSymbolAddress((void**)&s0h,    g_s0hi);
    cudaGetSymbolAddress((void**)&s0l,    g_s0lo);
    cudaGetSymbolAddress((void**)&s1h,    g_s1hi);
    cudaGetSymbolAddress((void**)&s1l,    g_s1lo);
    cudaGetSymbolAddress((void**)&w1h,    g_w1hi);
    cudaGetSymbolAddress((void**)&w1l,    g_w1lo);
    cudaGetSymbolAddress((void**)&w2h,    g_w2hi);
    cudaGetSymbolAddress((void**)&w2l,    g_w2lo);
    cudaGetSymbolAddress((void**)&woh,    g_wohi);
    cudaGetSymbolAddress((void**)&wol,    g_wolo);
    cudaGetSymbolAddress((void**)&wih,    g_wihi);
    cudaGetSymbolAddress((void**)&wil,    g_wilo);
    cudaGetSymbolAddress((void**)&whh,    g_whhi);
    cudaGetSymbolAddress((void**)&whl,    g_whlo);

    cudaFuncSetAttribute(gemm_f16<128,2>, cudaFuncAttributeMaxDynamicSharedMemorySize, SMEM_P2_128);
    cudaFuncSetAttribute(gemm_f16<128,3>, cudaFuncAttributeMaxDynamicSharedMemorySize, SMEM_P3_128);
    cudaFuncSetAttribute(gemm_rk4,        cudaFuncAttributeMaxDynamicSharedMemorySize, SMEM_P2_128);
    cudaFuncSetAttribute(gru_fused,       cudaFuncAttributeMaxDynamicSharedMemorySize, GRU_SMEM);

    const int M = (int)NROWS;

    // Weight prep (transpose + fp16 split). W1 uses only its first 512 rows.
    wsplit<<<(512 * 512) / 256, 256>>>(ode_W1,   w1h, w1l, 512, 512);
    wsplit<<<(512 * 512) / 256, 256>>>(ode_W2,   w2h, w2l, 512, 512);
    wsplit<<<(512 * 512) / 256, 256>>>(ode_Wout, woh, wol, 512, 512);
    wsplit<<<(512 * 1536) / 256, 256>>>(W_ih, wih, wil, 512, 1536);
    wsplit<<<(512 * 1536) / 256, 256>>>(W_hh, whh, whl, 512, 1536);
    make_bias_all<<<32, 256>>>(p_beff, ode_b1, ode_W1 + 512 * 512);

    // obs embedding (ODE initial conditions)
    obs_embed<<<M, 256>>>(xs, obs_W, obs_b, obs_lg, obs_lb, p_h, p_hhi, p_hlo);

    dim3 gBig(512 / 128,  M / 128);       // (4, 512)
    dim3 gGi (1536 / 128, M / 128);       // (12, 512)
    const int LNG = M / 8;

    // Batched RK4 over ALL timesteps (effective batch 65536)
    for (int s = 0; s < 4; s++) {
        for (int st = 0; st < 4; st++) {
            const float* beff = p_beff + (size_t)(s * 4 + st) * 512;
            const __half* Ah = (st == 0) ? p_hhi : p_yhi;
            gemm_f16<128,2><<<gBig, 256, SMEM_P2_128>>>(Ah, Ah, w1h, w1l, beff, p_z, 512);
            ln_lrelu<<<LNG, 256>>>(p_z, ln1_g, ln1_b, p_xhi);
            gemm_f16<128,2><<<gBig, 256, SMEM_P2_128>>>(p_xhi, p_xhi, w2h, w2l, ode_b2, p_z, 512);
            ln_lrelu<<<LNG, 256>>>(p_z, ln2_g, ln2_b, p_xhi);
            if (st < 3) {
                const float wa = (st == 0) ? 1.f : 2.f;
                const float wy = (st == 2) ? 0.25f : 0.125f;
                gemm_rk4<<<gBig, 256, SMEM_P2_128>>>(p_xhi, woh, wol, ode_bout,
                                                     p_h, p_acc, p_yhi, p_hlo,
                                                     wa, wy, (st == 0) ? 0 : 1);
            } else {
                gemm_rk4<<<gBig, 256, SMEM_P2_128>>>(p_xhi, woh, wol, ode_bout,
                                                     p_h, p_acc, p_hhi, p_hlo,
                                                     1.f, 0.f, 2);
            }
        }
    }

    // Input gates for all timesteps in one GEMM (P3: near-exact)
    gemm_f16<128,3><<<gGi, 256, SMEM_P3_128>>>(p_hhi, p_hlo, wih, wil, b_ih, p_gi, 1536);

    // Sequential GRU: one fused kernel per step, ping-pong fp16 split state
    zero_state<<<(BATCH * HID) / 256, 256>>>(s0h, s0l);
    dim3 gGru(4, 32);
    for (int t = 0; t < T_STEPS; t++) {
        const __half* inH = (t & 1) ? s1h : s0h;
        const __half* inL = (t & 1) ? s1l : s0l;
        __half* outH = (t & 1) ? s0h : s1h;
        __half* outL = (t & 1) ? s0l : s1l;
        gru_fused<<<gGru, 256, GRU_SMEM>>>(inH, inL, whh, whl, b_hh,
                                           p_gi + (size_t)t * BATCH * G3, outH, outL);
    }

    // After t=63 (odd), final state is in s0
    copy_out<<<(BATCH * HID) / 256, 256>>>((float*)d_out, s0h, s0l);
}

// round 12
// speedup vs baseline: 1.7234x; 1.7234x over previous
#include <cuda_runtime.h>
#include <cuda_fp16.h>
#include <cstdint>
#include <cstddef>

// ---------------------------------------------------------------------------
// Dims
// ---------------------------------------------------------------------------
constexpr int    T_STEPS = 64;
constexpr int    BATCH   = 1024;
constexpr int    HID     = 512;
constexpr int    G3      = 3 * HID;                  // 1536
constexpr size_t NROWS   = (size_t)T_STEPS * BATCH;  // 65536
constexpr int    KDIM    = 512;

// ---------------------------------------------------------------------------
// PTX helpers (arch-unconditional, sm_80-era)
// ---------------------------------------------------------------------------
__device__ __forceinline__ uint32_t smem_u32(const void* p) {
    uint32_t a;
    asm("{ .reg .u64 t; cvta.to.shared.u64 t, %1; cvt.u32.u64 %0, t; }"
        : "=r"(a) : "l"(p));
    return a;
}
#define CP16(s, g) \
    asm volatile("cp.async.cg.shared.global [%0], [%1], 16;\n" :: "r"(s), "l"(g) : "memory")
#define CP_COMMIT() asm volatile("cp.async.commit_group;\n" ::: "memory")
#define CP_WAIT_N(n) asm volatile("cp.async.wait_group %0;" :: "n"(n) : "memory")

#define LDM_X4(r, addr)                                                         \
    asm volatile("ldmatrix.sync.aligned.m8n8.x4.shared.b16 {%0,%1,%2,%3}, [%4];" \
        : "=r"((r)[0]), "=r"((r)[1]), "=r"((r)[2]), "=r"((r)[3]) : "r"(addr))

#define MMA_F16(d, a, b0, b1)                                                   \
    asm volatile("mma.sync.aligned.m16n8k16.row.col.f32.f16.f16.f32 "           \
        "{%0,%1,%2,%3}, {%4,%5,%6,%7}, {%8,%9}, {%0,%1,%2,%3};"                 \
        : "+f"((d)[0]), "+f"((d)[1]), "+f"((d)[2]), "+f"((d)[3])                \
        : "r"((a)[0]), "r"((a)[1]), "r"((a)[2]), "r"((a)[3]), "r"(b0), "r"(b1))

// ---------------------------------------------------------------------------
// Scratch
// ---------------------------------------------------------------------------
__device__ float g_h   [NROWS * HID];     // fp32 ODE state
__device__ float g_acc [NROWS * HID];     // RK4 accumulator
__device__ float g_z   [NROWS * HID];     // fp32 GEMM out (pre-LN)
__device__ float g_gi  [NROWS * G3];
__device__ float g_gh  [BATCH * G3];
__device__ float g_hst [BATCH * HID];
__device__ float g_beff[16 * HID];        // all 16 time-folded W1 biases

__device__ __half g_hhi[NROWS * HID], g_hlo[NROWS * HID];  // h state split
__device__ __half g_xhi[NROWS * HID];                      // LN outputs (hi only)
__device__ __half g_yhi[NROWS * HID];                      // RK4 Y output (hi only)
__device__ __half g_shi[BATCH * HID], g_slo[BATCH * HID];  // GRU state split
__device__ __half g_w1hi[HID * HID];
__device__ __half g_w2hi[HID * HID];
__device__ __half g_wohi[HID * HID],  g_wolo[HID * HID];
__device__ __half g_wihi[G3 * HID],   g_wilo[G3 * HID];
__device__ __half g_whhi[G3 * HID],   g_whlo[G3 * HID];

// ---------------------------------------------------------------------------
// fp16 split helpers
// ---------------------------------------------------------------------------
__device__ __forceinline__ void split1h(float v, __half& hi, __half& lo) {
    hi = __float2half(v);
    lo = __float2half(v - __half2float(hi));
}
__device__ __forceinline__ void split_store_pair(__half* Hi, __half* Lo,
                                                 size_t i, float a, float b) {
    __half2 h, l;
    split1h(a, h.x, l.x); split1h(b, h.y, l.y);
    *reinterpret_cast<__half2*>(Hi + i) = h;
    *reinterpret_cast<__half2*>(Lo + i) = l;
}

// ===========================================================================
// fp16 split GEMM: C[M,N] = A @ B^T + bias, B pre-transposed [N,512].
// PRODUCTS==1: C = Ah*Bh.  PRODUCTS==2: + Ah*Bl.  PRODUCTS==3: + Al*Bh.
// BM x 128 tile, BK=32, 16 chunks, 256 threads (8 warps 2Mx4N).
// ===========================================================================
template<int BM, int PRODUCTS>
__global__ void __launch_bounds__(256, PRODUCTS <= 2 ? 2 : 1)
gemm_f16(const __half* __restrict__ Ahi, const __half* __restrict__ Alo,
         const __half* __restrict__ Bhi, const __half* __restrict__ Blo,
         const float* __restrict__ bias, float* __restrict__ C, int N)
{
    constexpr int MF    = BM / 32;
    constexpr int AB    = BM * 64;
    constexpr int ASETS = (PRODUCTS == 3) ? 2 : 1;
    constexpr int BSETS = (PRODUCTS >= 2) ? 2 : 1;
    constexpr int STB   = ASETS * AB + BSETS * 8192;
    constexpr int S     = (PRODUCTS == 3) ? 3 : 4;

    extern __shared__ char smem[];
    const uint32_t sb = smem_u32(smem);
    const int tid  = threadIdx.x;
    const int lane = tid & 31;
    const int wid  = tid >> 5;
    const int wm   = (wid >> 2) * (BM / 2);
    const int wn   = (wid & 3) * 32;
    const size_t bm = (size_t)blockIdx.y * BM;
    const size_t bn = (size_t)blockIdx.x * 128;

    float acc[MF][4][4];
    #pragma unroll
    for (int i = 0; i < MF; i++)
        #pragma unroll
        for (int j = 0; j < 4; j++)
            #pragma unroll
            for (int v = 0; v < 4; v++) acc[i][j][v] = 0.f;

    auto g2s = [&](int kc) {
        const uint32_t st = sb + (uint32_t)(kc % S) * STB;
        const int ko = kc * 32;
        const int c  = tid & 3;
        const int r0 = tid >> 2;
        #pragma unroll
        for (int i = 0; i < BM / 64; i++) {
            const int r = r0 + i * 64;
            const uint32_t sw = (uint32_t)(r * 64 + 16 * (c ^ ((r >> 1) & 3)));
            CP16(st + sw, Ahi + (bm + r) * KDIM + ko + c * 8);
            if constexpr (PRODUCTS == 3)
                CP16(st + AB + sw, Alo + (bm + r) * KDIM + ko + c * 8);
        }
        #pragma unroll
        for (int i = 0; i < 2; i++) {
            const int r = r0 + i * 64;
            const uint32_t sw = (uint32_t)(r * 64 + 16 * (c ^ ((r >> 1) & 3)));
            CP16(st + ASETS * AB + sw, Bhi + (bn + r) * KDIM + ko + c * 8);
            if constexpr (PRODUCTS >= 2)
                CP16(st + ASETS * AB + 8192 + sw, Blo + (bn + r) * KDIM + ko + c * 8);
        }
        CP_COMMIT();
    };

    #pragma unroll
    for (int kc = 0; kc < S - 1; kc++) g2s(kc);

    #pragma unroll 1
    for (int kc = 0; kc < 16; kc++) {
        if constexpr (S == 4) {
            if (kc <= 13) CP_WAIT_N(2);
            else if (kc == 14) CP_WAIT_N(1);
            else CP_WAIT_N(0);
        } else {
            if (kc <= 14) CP_WAIT_N(1);
            else CP_WAIT_N(0);
        }
        __syncthreads();
        if (kc + S - 1 < 16) g2s(kc + S - 1);
        const uint32_t st = sb + (uint32_t)(kc % S) * STB;

        #pragma unroll
        for (int s = 0; s < 2; s++) {
            uint32_t ah[MF][4], al[MF][4], bh[2][4], bl[2][4];
            #pragma unroll
            for (int mf = 0; mf < MF; mf++) {
                const int ar = wm + mf * 16 + (lane & 15);
                const int ac = s * 2 + (lane >> 4);
                const uint32_t sw = (uint32_t)(ar * 64 + 16 * (ac ^ ((ar >> 1) & 3)));
                LDM_X4(ah[mf], st + sw);
                if constexpr (PRODUCTS == 3) LDM_X4(al[mf], st + AB + sw);
            }
            #pragma unroll
            for (int nf16 = 0; nf16 < 2; nf16++) {
                const int br = wn + nf16 * 16 + (lane & 7) + ((lane >> 4) & 1) * 8;
                const int bc = s * 2 + ((lane >> 3) & 1);
                const uint32_t sw = (uint32_t)(br * 64 + 16 * (bc ^ ((br >> 1) & 3)));
                LDM_X4(bh[nf16], st + ASETS * AB + sw);
                if constexpr (PRODUCTS >= 2)
                    LDM_X4(bl[nf16], st + ASETS * AB + 8192 + sw);
            }
            #pragma unroll
            for (int mf = 0; mf < MF; mf++)
                #pragma unroll
                for (int nf = 0; nf < 4; nf++) {
                    const uint32_t b0h = bh[nf >> 1][(nf & 1) * 2];
                    const uint32_t b1h = bh[nf >> 1][(nf & 1) * 2 + 1];
                    MMA_F16(acc[mf][nf], ah[mf], b0h, b1h);
                    if constexpr (PRODUCTS >= 2)
                        MMA_F16(acc[mf][nf], ah[mf],
                                bl[nf >> 1][(nf & 1) * 2], bl[nf >> 1][(nf & 1) * 2 + 1]);
                    if constexpr (PRODUCTS == 3)
                        MMA_F16(acc[mf][nf], al[mf], b0h, b1h);
                }
        }
    }

    #pragma unroll
    for (int mf = 0; mf < MF; mf++) {
        const size_t r0 = bm + wm + mf * 16 + (lane >> 2);
        #pragma unroll
        for (int nf = 0; nf < 4; nf++) {
            const int col = wn + nf * 8 + (lane & 3) * 2;
            const float b0 = bias[bn + col], b1 = bias[bn + col + 1];
            *reinterpret_cast<float2*>(C + r0 * N + bn + col) =
                make_float2(acc[mf][nf][0] + b0, acc[mf][nf][1] + b1);
            *reinterpret_cast<float2*>(C + (r0 + 8) * N + bn + col) =
                make_float2(acc[mf][nf][2] + b0, acc[mf][nf][3] + b1);
        }
    }
}

constexpr int SMEM_P1_128 = 4 * (128 * 64 + 8192);        // 65536
constexpr int SMEM_P2_128 = 4 * (128 * 64 + 16384);       // 98304
constexpr int SMEM_P3_128 = 3 * (2 * 128 * 64 + 16384);   // 98304
constexpr int SMEM_P3_64  = 3 * (2 * 64 * 64 + 16384);    // 73728

// ===========================================================================
// Wout GEMM (P2, BM=128, N=512) + RK4 epilogue.
// mode0: Acc=K, Y=H+wy*K -> Yhi.  mode1: Acc+=wacc*K, Y -> Yhi.
// mode2: H+=(Acc+K)/24 -> H fp32, Yhi=hi(H), Hlo2=lo(H).
// ===========================================================================
__global__ void __launch_bounds__(256, 2)
gemm_rk4(const __half* __restrict__ Ahi,
         const __half* __restrict__ Bhi, const __half* __restrict__ Blo,
         const float* __restrict__ bias,
         float* __restrict__ H, float* __restrict__ Acc,
         __half* __restrict__ Yhi, __half* __restrict__ Hlo2,
         float wacc, float wy, int mode)
{
    constexpr int AB  = 128 * 64;
    constexpr int STB = AB + 16384;     // 24576
    extern __shared__ char smem[];
    const uint32_t sb = smem_u32(smem);
    const int tid  = threadIdx.x;
    const int lane = tid & 31;
    const int wid  = tid >> 5;
    const int wm   = (wid >> 2) * 64;
    const int wn   = (wid & 3) * 32;
    const size_t bm = (size_t)blockIdx.y * 128;
    const size_t bn = (size_t)blockIdx.x * 128;

    float acc[4][4][4];
    #pragma unroll
    for (int i = 0; i < 4; i++)
        #pragma unroll
        for (int j = 0; j < 4; j++)
            #pragma unroll
            for (int v = 0; v < 4; v++) acc[i][j][v] = 0.f;

    auto g2s = [&](int kc) {
        const uint32_t st = sb + (uint32_t)(kc & 3) * STB;
        const int ko = kc * 32;
        const int c  = tid & 3;
        const int r0 = tid >> 2;
        #pragma unroll
        for (int i = 0; i < 2; i++) {
            const int r = r0 + i * 64;
            const uint32_t sw = (uint32_t)(r * 64 + 16 * (c ^ ((r >> 1) & 3)));
            CP16(st + sw,              Ahi + (bm + r) * KDIM + ko + c * 8);
            CP16(st + AB + sw,         Bhi + (bn + r) * KDIM + ko + c * 8);
            CP16(st + AB + 8192 + sw,  Blo + (bn + r) * KDIM + ko + c * 8);
        }
        CP_COMMIT();
    };

    #pragma unroll
    for (int kc = 0; kc < 3; kc++) g2s(kc);

    #pragma unroll 1
    for (int kc = 0; kc < 16; kc++) {
        if (kc <= 13) CP_WAIT_N(2);
        else if (kc == 14) CP_WAIT_N(1);
        else CP_WAIT_N(0);
        __syncthreads();
        if (kc + 3 < 16) g2s(kc + 3);
        const uint32_t st = sb + (uint32_t)(kc & 3) * STB;

        #pragma unroll
        for (int s = 0; s < 2; s++) {
            uint32_t ah[4][4], bh[2][4], bl[2][4];
            #pragma unroll
            for (int mf = 0; mf < 4; mf++) {
                const int ar = wm + mf * 16 + (lane & 15);
                const int ac = s * 2 + (lane >> 4);
                LDM_X4(ah[mf], st + (uint32_t)(ar * 64 + 16 * (ac ^ ((ar >> 1) & 3))));
            }
            #pragma unroll
            for (int nf16 = 0; nf16 < 2; nf16++) {
                const int br = wn + nf16 * 16 + (lane & 7) + ((lane >> 4) & 1) * 8;
                const int bc = s * 2 + ((lane >> 3) & 1);
                const uint32_t sw = (uint32_t)(br * 64 + 16 * (bc ^ ((br >> 1) & 3)));
                LDM_X4(bh[nf16], st + AB + sw);
                LDM_X4(bl[nf16], st + AB + 8192 + sw);
            }
            #pragma unroll
            for (int mf = 0; mf < 4; mf++)
                #pragma unroll
                for (int nf = 0; nf < 4; nf++) {
                    MMA_F16(acc[mf][nf], ah[mf],
                            bh[nf >> 1][(nf & 1) * 2], bh[nf >> 1][(nf & 1) * 2 + 1]);
                    MMA_F16(acc[mf][nf], ah[mf],
                            bl[nf >> 1][(nf & 1) * 2], bl[nf >> 1][(nf & 1) * 2 + 1]);
                }
        }
    }

    // RK4 epilogue
    #pragma unroll
    for (int mf = 0; mf < 4; mf++)
        #pragma unroll
        for (int nf = 0; nf < 4; nf++) {
            const int col = wn + nf * 8 + 2 * (lane & 3);
            const float b0 = bias[bn + col], b1 = bias[bn + col + 1];
            #pragma unroll
            for (int hv = 0; hv < 2; hv++) {
                const size_t row = bm + wm + mf * 16 + (lane >> 2) + 8 * hv;
                const size_t ix = row * 512 + bn + col;
                const float k0 = acc[mf][nf][2 * hv]     + b0;
                const float k1 = acc[mf][nf][2 * hv + 1] + b1;
                if (mode == 0) {
                    *reinterpret_cast<float2*>(Acc + ix) = make_float2(k0, k1);
                    const float2 h2 = *reinterpret_cast<const float2*>(H + ix);
                    __half2 y;
                    y.x = __float2half(fmaf(wy, k0, h2.x));
                    y.y = __float2half(fmaf(wy, k1, h2.y));
                    *reinterpret_cast<__half2*>(Yhi + ix) = y;
                } else if (mode == 1) {
                    float2 a2 = *reinterpret_cast<const float2*>(Acc + ix);
                    a2.x = fmaf(wacc, k0, a2.x); a2.y = fmaf(wacc, k1, a2.y);
                    *reinterpret_cast<float2*>(Acc + ix) = a2;
                    const float2 h2 = *reinterpret_cast<const float2*>(H + ix);
                    __half2 y;
                    y.x = __float2half(fmaf(wy, k0, h2.x));
                    y.y = __float2half(fmaf(wy, k1, h2.y));
                    *reinterpret_cast<__half2*>(Yhi + ix) = y;
                } else {
                    const float2 a2 = *reinterpret_cast<const float2*>(Acc + ix);
                    float2 h2 = *reinterpret_cast<const float2*>(H + ix);
                    const float cc = 1.0f / 24.0f;
                    h2.x = fmaf(a2.x + k0, cc, h2.x);
                    h2.y = fmaf(a2.y + k1, cc, h2.y);
                    *reinterpret_cast<float2*>(H + ix) = h2;
                    split_store_pair(Yhi, Hlo2, ix, h2.x, h2.y);
                }
            }
        }
}

// ---------------------------------------------------------------------------
// LayerNorm(512)+LeakyReLU, warp-per-row. fp32 in -> fp16 HI only.
// ---------------------------------------------------------------------------
__global__ void ln_lrelu(const float* __restrict__ Z,
                         const float* __restrict__ g, const float* __restrict__ b,
                         __half* __restrict__ Xhi)
{
    const int lane = threadIdx.x & 31;
    const size_t row = (size_t)blockIdx.x * 8 + (threadIdx.x >> 5);
    const float* z = Z + row * 512;

    float4 v[4];
    #pragma unroll
    for (int i = 0; i < 4; i++)
        v[i] = *reinterpret_cast<const float4*>(z + i * 128 + lane * 4);

    float s = 0.f;
    #pragma unroll
    for (int i = 0; i < 4; i++) s += v[i].x + v[i].y + v[i].z + v[i].w;
    #pragma unroll
    for (int o = 16; o > 0; o >>= 1) s += __shfl_xor_sync(0xffffffffu, s, o);
    const float mean = s * (1.0f / 512.0f);

    float q = 0.f;
    #pragma unroll
    for (int i = 0; i < 4; i++) {
        const float d0 = v[i].x - mean, d1 = v[i].y - mean;
        const float d2 = v[i].z - mean, d3 = v[i].w - mean;
        q += d0 * d0 + d1 * d1 + d2 * d2 + d3 * d3;
    }
    #pragma unroll
    for (int o = 16; o > 0; o >>= 1) q += __shfl_xor_sync(0xffffffffu, q, o);
    const float rstd = rsqrtf(q * (1.0f / 512.0f) + 1e-5f);

    #pragma unroll
    for (int i = 0; i < 4; i++) {
        const int c = i * 128 + lane * 4;
        const float4 gg = *reinterpret_cast<const float4*>(g + c);
        const float4 bb = *reinterpret_cast<const float4*>(b + c);
        float y0 = fmaf((v[i].x - mean) * rstd, gg.x, bb.x);
        float y1 = fmaf((v[i].y - mean) * rstd, gg.y, bb.y);
        float y2 = fmaf((v[i].z - mean) * rstd, gg.z, bb.z);
        float y3 = fmaf((v[i].w - mean) * rstd, gg.w, bb.w);
        y0 = (y0 > 0.f) ? y0 : 0.01f * y0;
        y1 = (y1 > 0.f) ? y1 : 0.01f * y1;
        y2 = (y2 > 0.f) ? y2 : 0.01f * y2;
        y3 = (y3 > 0.f) ? y3 : 0.01f * y3;
        __half2 p0; p0.x = __float2half(y0); p0.y = __float2half(y1);
        __half2 p1; p1.x = __float2half(y2); p1.y = __float2half(y3);
        *reinterpret_cast<__half2*>(Xhi + row * 512 + c)     = p0;
        *reinterpret_cast<__half2*>(Xhi + row * 512 + c + 2) = p1;
    }
}

// ---------------------------------------------------------------------------
// obs -> hidden: Linear(8->512)+LN+LeakyReLU; fp32 H + fp16 split
// ---------------------------------------------------------------------------
__device__ __forceinline__ float block_sum512(float x, float* red, int tid) {
    #pragma unroll
    for (int o = 16; o > 0; o >>= 1) x += __shfl_xor_sync(0xffffffffu, x, o);
    __syncthreads();
    if ((tid & 31) == 0) red[tid >> 5] = x;
    __syncthreads();
    float t = 0.f;
    #pragma unroll
    for (int i = 0; i < 8; i++) t += red[i];
    return t;
}

__global__ void obs_embed(const float* __restrict__ xs, const float* __restrict__ W,
                          const float* __restrict__ bias,
                          const float* __restrict__ lg, const float* __restrict__ lb,
                          float* __restrict__ H,
                          __half* __restrict__ Hhi, __half* __restrict__ Hlo)
{
    __shared__ float xv[8];
    __shared__ float red[8];
    const size_t row = blockIdx.x;
    const int tid = threadIdx.x;
    const int c = 2 * tid;
    if (tid < 8) xv[tid] = xs[row * 8 + tid];
    __syncthreads();
    float2 v = *reinterpret_cast<const float2*>(bias + c);
    #pragma unroll
    for (int k = 0; k < 8; k++) {
        float2 w = *reinterpret_cast<const float2*>(W + k * 512 + c);
        v.x = fmaf(xv[k], w.x, v.x);
        v.y = fmaf(xv[k], w.y, v.y);
    }
    const float mean = block_sum512(v.x + v.y, red, tid) * (1.f / 512.f);
    const float d0 = v.x - mean, d1 = v.y - mean;
    const float rstd = rsqrtf(block_sum512(d0 * d0 + d1 * d1, red, tid) * (1.f / 512.f) + 1e-5f);
    const float2 gg = *reinterpret_cast<const float2*>(lg + c);
    const float2 bb = *reinterpret_cast<const float2*>(lb + c);
    float y0 = fmaf(d0 * rstd, gg.x, bb.x);
    float y1 = fmaf(d1 * rstd, gg.y, bb.y);
    y0 = (y0 > 0.f) ? y0 : 0.01f * y0;
    y1 = (y1 > 0.f) ? y1 : 0.01f * y1;
    *reinterpret_cast<float2*>(H + row * 512 + c) = make_float2(y0, y1);
    split_store_pair(Hhi, Hlo, row * 512 + c, y0, y1);
}

// All 16 time-folded W1 biases at once
__global__ void make_bias_all(float* __restrict__ beff, const float* __restrict__ b1,
                              const float* __restrict__ w1_last)
{
    const int i = blockIdx.x * 256 + threadIdx.x;   // < 16*512
    const int idx = i >> 9;
    const int n = i & 511;
    const int s = idx >> 2, st = idx & 3;
    const float toff[4] = {0.f, 0.125f, 0.125f, 0.25f};
    const float tt = (float)s * 0.25f + toff[st];
    beff[i] = fmaf(tt, w1_last[n], b1[n]);
}

// GRU elementwise (torch gate order r,z,n); updates fp32 h + fp16 split
__global__ void gru_step(const float* __restrict__ GI, const float* __restrict__ GH,
                         float* __restrict__ Hs,
                         __half* __restrict__ Shi, __half* __restrict__ Slo)
{
    const int i   = blockIdx.x * blockDim.x + threadIdx.x;
    const int row = i >> 9;
    const int n   = i & 511;
    const float* gi = GI + (size_t)row * 1536;
    const float* gh = GH + (size_t)row * 1536;
    const float r  = 1.f / (1.f + expf(-(gi[n]       + gh[n])));
    const float z  = 1.f / (1.f + expf(-(gi[512 + n] + gh[512 + n])));
    const float nn = tanhf(gi[1024 + n] + r * gh[1024 + n]);
    const float h  = (1.f - z) * nn + z * Hs[i];
    Hs[i] = h;
    split1h(h, Shi[i], Slo[i]);
}

// W[K,N] (fp32 row-major) -> Whi/Wlo[N,K] fp16 split (transposed); Wlo optional
__global__ void wsplit(const float* __restrict__ W,
                       __half* __restrict__ Whi, __half* __restrict__ Wlo,
                       int K, int N)
{
    int idx = blockIdx.x * blockDim.x + threadIdx.x;
    if (idx >= K * N) return;
    int k = idx / N, n = idx % N;
    __half hi, lo;
    split1h(W[idx], hi, lo);
    Whi[(size_t)n * K + k] = hi;
    if (Wlo) Wlo[(size_t)n * K + k] = lo;
}

__global__ void zero_state(float* __restrict__ h,
                           __half* __restrict__ hi, __half* __restrict__ lo)
{
    int i = blockIdx.x * blockDim.x + threadIdx.x;
    h[i] = 0.f;
    hi[i] = __float2half(0.f);
    lo[i] = __float2half(0.f);
}

__global__ void copy_kernel(float* __restrict__ dst, const float* __restrict__ src)
{
    int i = blockIdx.x * blockDim.x + threadIdx.x;
    dst[i] = src[i];
}

// ---------------------------------------------------------------------------
// Launch
// ---------------------------------------------------------------------------
extern "C" void kernel_launch(void* const* d_in, const int* in_sizes, int n_in,
                              void* d_out, int out_size)
{
    const float* xs       = (const float*)d_in[0];
    const float* obs_W    = (const float*)d_in[1];
    const float* obs_b    = (const float*)d_in[2];
    const float* obs_lg   = (const float*)d_in[3];
    const float* obs_lb   = (const float*)d_in[4];
    const float* ode_W1   = (const float*)d_in[5];   // [513, 512]
    const float* ode_b1   = (const float*)d_in[6];
    const float* ln1_g    = (const float*)d_in[7];
    const float* ln1_b    = (const float*)d_in[8];
    const float* ode_W2   = (const float*)d_in[9];
    const float* ode_b2   = (const float*)d_in[10];
    const float* ln2_g    = (const float*)d_in[11];
    const float* ln2_b    = (const float*)d_in[12];
    const float* ode_Wout = (const float*)d_in[13];
    const float* ode_bout = (const float*)d_in[14];
    const float* W_ih     = (const float*)d_in[15];  // [512, 1536]
    const float* b_ih     = (const float*)d_in[16];
    const float* W_hh     = (const float*)d_in[17];
    const float* b_hh     = (const float*)d_in[18];

    float *p_h, *p_acc, *p_z, *p_gi, *p_gh, *p_hst, *p_beff;
    __half *p_hhi, *p_hlo, *p_xhi, *p_yhi, *p_shi, *p_slo;
    __half *w1h, *w2h, *woh, *wol, *wih, *wil, *whh, *whl;
    cudaGetSymbolAddress((void**)&p_h,    g_h);
    cudaGetSymbolAddress((void**)&p_acc,  g_acc);
    cudaGetSymbolAddress((void**)&p_z,    g_z);
    cudaGetSymbolAddress((void**)&p_gi,   g_gi);
    cudaGetSymbolAddress((void**)&p_gh,   g_gh);
    cudaGetSymbolAddress((void**)&p_hst,  g_hst);
    cudaGetSymbolAddress((void**)&p_beff, g_beff);
    cudaGetSymbolAddress((void**)&p_hhi,  g_hhi);
    cudaGetSymbolAddress((void**)&p_hlo,  g_hlo);
    cudaGetSymbolAddress((void**)&p_xhi,  g_xhi);
    cudaGetSymbolAddress((void**)&p_yhi,  g_yhi);
    cudaGetSymbolAddress((void**)&p_shi,  g_shi);
    cudaGetSymbolAddress((void**)&p_slo,  g_slo);
    cudaGetSymbolAddress((void**)&w1h,    g_w1hi);
    cudaGetSymbolAddress((void**)&w2h,    g_w2hi);
    cudaGetSymbolAddress((void**)&woh,    g_wohi);
    cudaGetSymbolAddress((void**)&wol,    g_wolo);
    cudaGetSymbolAddress((void**)&wih,    g_wihi);
    cudaGetSymbolAddress((void**)&wil,    g_wilo);
    cudaGetSymbolAddress((void**)&whh,    g_whhi);
    cudaGetSymbolAddress((void**)&whl,    g_whlo);

    cudaFuncSetAttribute(gemm_f16<128,1>, cudaFuncAttributeMaxDynamicSharedMemorySize, SMEM_P1_128);
    cudaFuncSetAttribute(gemm_f16<128,3>, cudaFuncAttributeMaxDynamicSharedMemorySize, SMEM_P3_128);
    cudaFuncSetAttribute(gemm_f16<64,3>,  cudaFuncAttributeMaxDynamicSharedMemorySize, SMEM_P3_64);
    cudaFuncSetAttribute(gemm_rk4,        cudaFuncAttributeMaxDynamicSharedMemorySize, SMEM_P2_128);

    const int M = (int)NROWS;
    __half* nil = nullptr;

    // Weight prep (transpose + fp16 split). W1/W2 need hi only (P1 layers).
    wsplit<<<(512 * 512) / 256, 256>>>(ode_W1,   w1h, nil, 512, 512);
    wsplit<<<(512 * 512) / 256, 256>>>(ode_W2,   w2h, nil, 512, 512);
    wsplit<<<(512 * 512) / 256, 256>>>(ode_Wout, woh, wol, 512, 512);
    wsplit<<<(512 * 1536) / 256, 256>>>(W_ih, wih, wil, 512, 1536);
    wsplit<<<(512 * 1536) / 256, 256>>>(W_hh, whh, whl, 512, 1536);
    make_bias_all<<<32, 256>>>(p_beff, ode_b1, ode_W1 + 512 * 512);

    // obs embedding (ODE initial conditions)
    obs_embed<<<M, 256>>>(xs, obs_W, obs_b, obs_lg, obs_lb, p_h, p_hhi, p_hlo);

    dim3 gBig(512 / 128,  M / 128);       // (4, 512)
    dim3 gGi (1536 / 128, M / 128);       // (12, 512)
    dim3 gGru(1536 / 128, BATCH / 64);    // (12, 16)
    const int LNG = M / 8;

    // Batched RK4 over ALL timesteps (effective batch 65536)
    for (int s = 0; s < 4; s++) {
        for (int st = 0; st < 4; st++) {
            const float* beff = p_beff + (size_t)(s * 4 + st) * 512;
            const __half* Ah = (st == 0) ? p_hhi : p_yhi;
            gemm_f16<128,1><<<gBig, 256, SMEM_P1_128>>>(Ah, Ah, w1h, w1h, beff, p_z, 512);
            ln_lrelu<<<LNG, 256>>>(p_z, ln1_g, ln1_b, p_xhi);
            gemm_f16<128,1><<<gBig, 256, SMEM_P1_128>>>(p_xhi, p_xhi, w2h, w2h, ode_b2, p_z, 512);
            ln_lrelu<<<LNG, 256>>>(p_z, ln2_g, ln2_b, p_xhi);
            if (st < 3) {
                const float wa = (st == 0) ? 1.f : 2.f;
                const float wy = (st == 2) ? 0.25f : 0.125f;
                gemm_rk4<<<gBig, 256, SMEM_P2_128>>>(p_xhi, woh, wol, ode_bout,
                                                     p_h, p_acc, p_yhi, p_hlo,
                                                     wa, wy, (st == 0) ? 0 : 1);
            } else {
                gemm_rk4<<<gBig, 256, SMEM_P2_128>>>(p_xhi, woh, wol, ode_bout,
                                                     p_h, p_acc, p_hhi, p_hlo,
                                                     1.f, 0.f, 2);
            }
        }
    }

    // Input gates for all timesteps in one GEMM (P3: near-exact)
    gemm_f16<128,3><<<gGi, 256, SMEM_P3_128>>>(p_hhi, p_hlo, wih, wil, b_ih, p_gi, 1536);

    // Sequential GRU: proven two-kernel scheme (P3 GEMM + elementwise)
    zero_state<<<(BATCH * HID) / 256, 256>>>(p_hst, p_shi, p_slo);
    for (int t = 0; t < T_STEPS; t++) {
        gemm_f16<64,3><<<gGru, 256, SMEM_P3_64>>>(p_shi, p_slo, whh, whl, b_hh, p_gh, 1536);
        gru_step<<<(BATCH * HID) / 256, 256>>>(p_gi + (size_t)t * BATCH * G3, p_gh,
                                               p_hst, p_shi, p_slo);
    }

    copy_kernel<<<(BATCH * HID) / 256, 256>>>((float*)d_out, p_hst);
}

// round 14
// speedup vs baseline: 1.8455x; 1.0708x over previous
#include <cuda_runtime.h>
#include <cuda_fp16.h>
#include <cstdint>
#include <cstddef>

// ---------------------------------------------------------------------------
// Dims
// ---------------------------------------------------------------------------
constexpr int    T_STEPS = 64;
constexpr int    BATCH   = 1024;
constexpr int    HID     = 512;
constexpr int    G3      = 3 * HID;                  // 1536
constexpr size_t NROWS   = (size_t)T_STEPS * BATCH;  // 65536
constexpr int    KDIM    = 512;

// ---------------------------------------------------------------------------
// PTX helpers (arch-unconditional, sm_80-era)
// ---------------------------------------------------------------------------
__device__ __forceinline__ uint32_t smem_u32(const void* p) {
    uint32_t a;
    asm("{ .reg .u64 t; cvta.to.shared.u64 t, %1; cvt.u32.u64 %0, t; }"
        : "=r"(a) : "l"(p));
    return a;
}
#define CP16(s, g) \
    asm volatile("cp.async.cg.shared.global [%0], [%1], 16;\n" :: "r"(s), "l"(g) : "memory")
#define CP_COMMIT() asm volatile("cp.async.commit_group;\n" ::: "memory")
#define CP_WAIT_N(n) asm volatile("cp.async.wait_group %0;" :: "n"(n) : "memory")

#define LDM_X4(r, addr)                                                         \
    asm volatile("ldmatrix.sync.aligned.m8n8.x4.shared.b16 {%0,%1,%2,%3}, [%4];" \
        : "=r"((r)[0]), "=r"((r)[1]), "=r"((r)[2]), "=r"((r)[3]) : "r"(addr))

#define MMA_F16(d, a, b0, b1)                                                   \
    asm volatile("mma.sync.aligned.m16n8k16.row.col.f32.f16.f16.f32 "           \
        "{%0,%1,%2,%3}, {%4,%5,%6,%7}, {%8,%9}, {%0,%1,%2,%3};"                 \
        : "+f"((d)[0]), "+f"((d)[1]), "+f"((d)[2]), "+f"((d)[3])                \
        : "r"((a)[0]), "r"((a)[1]), "r"((a)[2]), "r"((a)[3]), "r"(b0), "r"(b1))

// ---------------------------------------------------------------------------
// Scratch
// ---------------------------------------------------------------------------
__device__ float g_h   [NROWS * HID];     // fp32 ODE state
__device__ float g_acc [NROWS * HID];     // RK4 accumulator
__device__ float g_z   [NROWS * HID];     // fp32 GEMM out (pre-LN)
__device__ float g_gi  [NROWS * G3];
__device__ float g_gh  [BATCH * G3];
__device__ float g_hst [BATCH * HID];
__device__ float g_beff[16 * HID];        // all 16 time-folded W1 biases

__device__ __half g_hhi[NROWS * HID], g_hlo[NROWS * HID];  // h state split
__device__ __half g_xhi[NROWS * HID];                      // LN outputs (hi only)
__device__ __half g_yhi[NROWS * HID];                      // RK4 Y output (hi only)
__device__ __half g_shi[BATCH * HID], g_slo[BATCH * HID];  // GRU state split
__device__ __half g_w1hi[HID * HID];
__device__ __half g_w2hi[HID * HID];
__device__ __half g_wohi[HID * HID];
__device__ __half g_wihi[G3 * HID],   g_wilo[G3 * HID];
__device__ __half g_whhi[G3 * HID],   g_whlo[G3 * HID];

// ---------------------------------------------------------------------------
// fp16 split helpers
// ---------------------------------------------------------------------------
__device__ __forceinline__ void split1h(float v, __half& hi, __half& lo) {
    hi = __float2half(v);
    lo = __float2half(v - __half2float(hi));
}
__device__ __forceinline__ void split_store_pair(__half* Hi, __half* Lo,
                                                 size_t i, float a, float b) {
    __half2 h, l;
    split1h(a, h.x, l.x); split1h(b, h.y, l.y);
    *reinterpret_cast<__half2*>(Hi + i) = h;
    *reinterpret_cast<__half2*>(Lo + i) = l;
}

// ===========================================================================
// fp16 split GEMM: C[M,N] = A @ B^T + bias, B pre-transposed [N,512].
// PRODUCTS==1: C = Ah*Bh.  PRODUCTS==2: + Ah*Bl.  PRODUCTS==3: + Al*Bh.
// BM x 128 tile, BK=32, 16 chunks, 256 threads (8 warps 2Mx4N).
// BM=64 P3 fits 2 CTAs/SM (73.7KB smem) — critical for GRU latency.
// ===========================================================================
template<int BM, int PRODUCTS>
__global__ void __launch_bounds__(256, (PRODUCTS <= 2 || BM == 64) ? 2 : 1)
gemm_f16(const __half* __restrict__ Ahi, const __half* __restrict__ Alo,
         const __half* __restrict__ Bhi, const __half* __restrict__ Blo,
         const float* __restrict__ bias, float* __restrict__ C, int N)
{
    constexpr int MF    = BM / 32;
    constexpr int AB    = BM * 64;
    constexpr int ASETS = (PRODUCTS == 3) ? 2 : 1;
    constexpr int BSETS = (PRODUCTS >= 2) ? 2 : 1;
    constexpr int STB   = ASETS * AB + BSETS * 8192;
    constexpr int S     = (PRODUCTS == 3) ? 3 : 4;

    extern __shared__ char smem[];
    const uint32_t sb = smem_u32(smem);
    const int tid  = threadIdx.x;
    const int lane = tid & 31;
    const int wid  = tid >> 5;
    const int wm   = (wid >> 2) * (BM / 2);
    const int wn   = (wid & 3) * 32;
    const size_t bm = (size_t)blockIdx.y * BM;
    const size_t bn = (size_t)blockIdx.x * 128;

    float acc[MF][4][4];
    #pragma unroll
    for (int i = 0; i < MF; i++)
        #pragma unroll
        for (int j = 0; j < 4; j++)
            #pragma unroll
            for (int v = 0; v < 4; v++) acc[i][j][v] = 0.f;

    auto g2s = [&](int kc) {
        const uint32_t st = sb + (uint32_t)(kc % S) * STB;
        const int ko = kc * 32;
        const int c  = tid & 3;
        const int r0 = tid >> 2;
        #pragma unroll
        for (int i = 0; i < BM / 64; i++) {
            const int r = r0 + i * 64;
            const uint32_t sw = (uint32_t)(r * 64 + 16 * (c ^ ((r >> 1) & 3)));
            CP16(st + sw, Ahi + (bm + r) * KDIM + ko + c * 8);
            if constexpr (PRODUCTS == 3)
                CP16(st + AB + sw, Alo + (bm + r) * KDIM + ko + c * 8);
        }
        #pragma unroll
        for (int i = 0; i < 2; i++) {
            const int r = r0 + i * 64;
            const uint32_t sw = (uint32_t)(r * 64 + 16 * (c ^ ((r >> 1) & 3)));
            CP16(st + ASETS * AB + sw, Bhi + (bn + r) * KDIM + ko + c * 8);
            if constexpr (PRODUCTS >= 2)
                CP16(st + ASETS * AB + 8192 + sw, Blo + (bn + r) * KDIM + ko + c * 8);
        }
        CP_COMMIT();
    };

    #pragma unroll
    for (int kc = 0; kc < S - 1; kc++) g2s(kc);

    #pragma unroll 1
    for (int kc = 0; kc < 16; kc++) {
        if constexpr (S == 4) {
            if (kc <= 13) CP_WAIT_N(2);
            else if (kc == 14) CP_WAIT_N(1);
            else CP_WAIT_N(0);
        } else {
            if (kc <= 14) CP_WAIT_N(1);
            else CP_WAIT_N(0);
        }
        __syncthreads();
        if (kc + S - 1 < 16) g2s(kc + S - 1);
        const uint32_t st = sb + (uint32_t)(kc % S) * STB;

        #pragma unroll
        for (int s = 0; s < 2; s++) {
            uint32_t ah[MF][4], al[MF][4], bh[2][4], bl[2][4];
            #pragma unroll
            for (int mf = 0; mf < MF; mf++) {
                const int ar = wm + mf * 16 + (lane & 15);
                const int ac = s * 2 + (lane >> 4);
                const uint32_t sw = (uint32_t)(ar * 64 + 16 * (ac ^ ((ar >> 1) & 3)));
                LDM_X4(ah[mf], st + sw);
                if constexpr (PRODUCTS == 3) LDM_X4(al[mf], st + AB + sw);
            }
            #pragma unroll
            for (int nf16 = 0; nf16 < 2; nf16++) {
                const int br = wn + nf16 * 16 + (lane & 7) + ((lane >> 4) & 1) * 8;
                const int bc = s * 2 + ((lane >> 3) & 1);
                const uint32_t sw = (uint32_t)(br * 64 + 16 * (bc ^ ((br >> 1) & 3)));
                LDM_X4(bh[nf16], st + ASETS * AB + sw);
                if constexpr (PRODUCTS >= 2)
                    LDM_X4(bl[nf16], st + ASETS * AB + 8192 + sw);
            }
            #pragma unroll
            for (int mf = 0; mf < MF; mf++)
                #pragma unroll
                for (int nf = 0; nf < 4; nf++) {
                    const uint32_t b0h = bh[nf >> 1][(nf & 1) * 2];
                    const uint32_t b1h = bh[nf >> 1][(nf & 1) * 2 + 1];
                    MMA_F16(acc[mf][nf], ah[mf], b0h, b1h);
                    if constexpr (PRODUCTS >= 2)
                        MMA_F16(acc[mf][nf], ah[mf],
                                bl[nf >> 1][(nf & 1) * 2], bl[nf >> 1][(nf & 1) * 2 + 1]);
                    if constexpr (PRODUCTS == 3)
                        MMA_F16(acc[mf][nf], al[mf], b0h, b1h);
                }
        }
    }

    #pragma unroll
    for (int mf = 0; mf < MF; mf++) {
        const size_t r0 = bm + wm + mf * 16 + (lane >> 2);
        #pragma unroll
        for (int nf = 0; nf < 4; nf++) {
            const int col = wn + nf * 8 + (lane & 3) * 2;
            const float b0 = bias[bn + col], b1 = bias[bn + col + 1];
            *reinterpret_cast<float2*>(C + r0 * N + bn + col) =
                make_float2(acc[mf][nf][0] + b0, acc[mf][nf][1] + b1);
            *reinterpret_cast<float2*>(C + (r0 + 8) * N + bn + col) =
                make_float2(acc[mf][nf][2] + b0, acc[mf][nf][3] + b1);
        }
    }
}

constexpr int SMEM_P1_128 = 4 * (128 * 64 + 8192);        // 65536
constexpr int SMEM_P3_128 = 3 * (2 * 128 * 64 + 16384);   // 98304
constexpr int SMEM_P3_64  = 3 * (2 * 64 * 64 + 16384);    // 73728
constexpr int SMEM_RK4    = 4 * (128 * 64 + 8192);        // 65536 (P1)

// ===========================================================================
// Wout GEMM (P1: Ah*Bh only, BM=128, N=512) + RK4 epilogue.
// mode0: Acc=K, Y=H+wy*K -> Yhi.  mode1: Acc+=wacc*K, Y -> Yhi.
// mode2: H+=(Acc+K)/24 -> H fp32, Yhi=hi(H), Hlo2=lo(H).
// ===========================================================================
__global__ void __launch_bounds__(256, 2)
gemm_rk4(const __half* __restrict__ Ahi,
         const __half* __restrict__ Bhi,
         const float* __restrict__ bias,
         float* __restrict__ H, float* __restrict__ Acc,
         __half* __restrict__ Yhi, __half* __restrict__ Hlo2,
         float wacc, float wy, int mode)
{
    constexpr int AB  = 128 * 64;
    constexpr int STB = AB + 8192;      // 16384
    extern __shared__ char smem[];
    const uint32_t sb = smem_u32(smem);
    const int tid  = threadIdx.x;
    const int lane = tid & 31;
    const int wid  = tid >> 5;
    const int wm   = (wid >> 2) * 64;
    const int wn   = (wid & 3) * 32;
    const size_t bm = (size_t)blockIdx.y * 128;
    const size_t bn = (size_t)blockIdx.x * 128;

    float acc[4][4][4];
    #pragma unroll
    for (int i = 0; i < 4; i++)
        #pragma unroll
        for (int j = 0; j < 4; j++)
            #pragma unroll
            for (int v = 0; v < 4; v++) acc[i][j][v] = 0.f;

    auto g2s = [&](int kc) {
        const uint32_t st = sb + (uint32_t)(kc & 3) * STB;
        const int ko = kc * 32;
        const int c  = tid & 3;
        const int r0 = tid >> 2;
        #pragma unroll
        for (int i = 0; i < 2; i++) {
            const int r = r0 + i * 64;
            const uint32_t sw = (uint32_t)(r * 64 + 16 * (c ^ ((r >> 1) & 3)));
            CP16(st + sw,      Ahi + (bm + r) * KDIM + ko + c * 8);
            CP16(st + AB + sw, Bhi + (bn + r) * KDIM + ko + c * 8);
        }
        CP_COMMIT();
    };

    #pragma unroll
    for (int kc = 0; kc < 3; kc++) g2s(kc);

    #pragma unroll 1
    for (int kc = 0; kc < 16; kc++) {
        if (kc <= 13) CP_WAIT_N(2);
        else if (kc == 14) CP_WAIT_N(1);
        else CP_WAIT_N(0);
        __syncthreads();
        if (kc + 3 < 16) g2s(kc + 3);
        const uint32_t st = sb + (uint32_t)(kc & 3) * STB;

        #pragma unroll
        for (int s = 0; s < 2; s++) {
            uint32_t ah[4][4], bh[2][4];
            #pragma unroll
            for (int mf = 0; mf < 4; mf++) {
                const int ar = wm + mf * 16 + (lane & 15);
                const int ac = s * 2 + (lane >> 4);
                LDM_X4(ah[mf], st + (uint32_t)(ar * 64 + 16 * (ac ^ ((ar >> 1) & 3))));
            }
            #pragma unroll
            for (int nf16 = 0; nf16 < 2; nf16++) {
                const int br = wn + nf16 * 16 + (lane & 7) + ((lane >> 4) & 1) * 8;
                const int bc = s * 2 + ((lane >> 3) & 1);
                LDM_X4(bh[nf16], st + AB + (uint32_t)(br * 64 + 16 * (bc ^ ((br >> 1) & 3))));
            }
            #pragma unroll
            for (int mf = 0; mf < 4; mf++)
                #pragma unroll
                for (int nf = 0; nf < 4; nf++)
                    MMA_F16(acc[mf][nf], ah[mf],
                            bh[nf >> 1][(nf & 1) * 2], bh[nf >> 1][(nf & 1) * 2 + 1]);
        }
    }

    // RK4 epilogue
    #pragma unroll
    for (int mf = 0; mf < 4; mf++)
        #pragma unroll
        for (int nf = 0; nf < 4; nf++) {
            const int col = wn + nf * 8 + 2 * (lane & 3);
            const float b0 = bias[bn + col], b1 = bias[bn + col + 1];
            #pragma unroll
            for (int hv = 0; hv < 2; hv++) {
                const size_t row = bm + wm + mf * 16 + (lane >> 2) + 8 * hv;
                const size_t ix = row * 512 + bn + col;
                const float k0 = acc[mf][nf][2 * hv]     + b0;
                const float k1 = acc[mf][nf][2 * hv + 1] + b1;
                if (mode == 0) {
                    *reinterpret_cast<float2*>(Acc + ix) = make_float2(k0, k1);
                    const float2 h2 = *reinterpret_cast<const float2*>(H + ix);
                    __half2 y;
                    y.x = __float2half(fmaf(wy, k0, h2.x));
                    y.y = __float2half(fmaf(wy, k1, h2.y));
                    *reinterpret_cast<__half2*>(Yhi + ix) = y;
                } else if (mode == 1) {
                    float2 a2 = *reinterpret_cast<const float2*>(Acc + ix);
                    a2.x = fmaf(wacc, k0, a2.x); a2.y = fmaf(wacc, k1, a2.y);
                    *reinterpret_cast<float2*>(Acc + ix) = a2;
                    const float2 h2 = *reinterpret_cast<const float2*>(H + ix);
                    __half2 y;
                    y.x = __float2half(fmaf(wy, k0, h2.x));
                    y.y = __float2half(fmaf(wy, k1, h2.y));
                    *reinterpret_cast<__half2*>(Yhi + ix) = y;
                } else {
                    const float2 a2 = *reinterpret_cast<const float2*>(Acc + ix);
                    float2 h2 = *reinterpret_cast<const float2*>(H + ix);
                    const float cc = 1.0f / 24.0f;
                    h2.x = fmaf(a2.x + k0, cc, h2.x);
                    h2.y = fmaf(a2.y + k1, cc, h2.y);
                    *reinterpret_cast<float2*>(H + ix) = h2;
                    split_store_pair(Yhi, Hlo2, ix, h2.x, h2.y);
                }
            }
        }
}

// ---------------------------------------------------------------------------
// LayerNorm(512)+LeakyReLU, warp-per-row. fp32 in -> fp16 HI only.
// ---------------------------------------------------------------------------
__global__ void ln_lrelu(const float* __restrict__ Z,
                         const float* __restrict__ g, const float* __restrict__ b,
                         __half* __restrict__ Xhi)
{
    const int lane = threadIdx.x & 31;
    const size_t row = (size_t)blockIdx.x * 8 + (threadIdx.x >> 5);
    const float* z = Z + row * 512;

    float4 v[4];
    #pragma unroll
    for (int i = 0; i < 4; i++)
        v[i] = *reinterpret_cast<const float4*>(z + i * 128 + lane * 4);

    float s = 0.f;
    #pragma unroll
    for (int i = 0; i < 4; i++) s += v[i].x + v[i].y + v[i].z + v[i].w;
    #pragma unroll
    for (int o = 16; o > 0; o >>= 1) s += __shfl_xor_sync(0xffffffffu, s, o);
    const float mean = s * (1.0f / 512.0f);

    float q = 0.f;
    #pragma unroll
    for (int i = 0; i < 4; i++) {
        const float d0 = v[i].x - mean, d1 = v[i].y - mean;
        const float d2 = v[i].z - mean, d3 = v[i].w - mean;
        q += d0 * d0 + d1 * d1 + d2 * d2 + d3 * d3;
    }
    #pragma unroll
    for (int o = 16; o > 0; o >>= 1) q += __shfl_xor_sync(0xffffffffu, q, o);
    const float rstd = rsqrtf(q * (1.0f / 512.0f) + 1e-5f);

    #pragma unroll
    for (int i = 0; i < 4; i++) {
        const int c = i * 128 + lane * 4;
        const float4 gg = *reinterpret_cast<const float4*>(g + c);
        const float4 bb = *reinterpret_cast<const float4*>(b + c);
        float y0 = fmaf((v[i].x - mean) * rstd, gg.x, bb.x);
        float y1 = fmaf((v[i].y - mean) * rstd, gg.y, bb.y);
        float y2 = fmaf((v[i].z - mean) * rstd, gg.z, bb.z);
        float y3 = fmaf((v[i].w - mean) * rstd, gg.w, bb.w);
        y0 = (y0 > 0.f) ? y0 : 0.01f * y0;
        y1 = (y1 > 0.f) ? y1 : 0.01f * y1;
        y2 = (y2 > 0.f) ? y2 : 0.01f * y2;
        y3 = (y3 > 0.f) ? y3 : 0.01f * y3;
        __half2 p0; p0.x = __float2half(y0); p0.y = __float2half(y1);
        __half2 p1; p1.x = __float2half(y2); p1.y = __float2half(y3);
        *reinterpret_cast<__half2*>(Xhi + row * 512 + c)     = p0;
        *reinterpret_cast<__half2*>(Xhi + row * 512 + c + 2) = p1;
    }
}

// ---------------------------------------------------------------------------
// obs -> hidden: Linear(8->512)+LN+LeakyReLU; fp32 H + fp16 split
// ---------------------------------------------------------------------------
__device__ __forceinline__ float block_sum512(float x, float* red, int tid) {
    #pragma unroll
    for (int o = 16; o > 0; o >>= 1) x += __shfl_xor_sync(0xffffffffu, x, o);
    __syncthreads();
    if ((tid & 31) == 0) red[tid >> 5] = x;
    __syncthreads();
    float t = 0.f;
    #pragma unroll
    for (int i = 0; i < 8; i++) t += red[i];
    return t;
}

__global__ void obs_embed(const float* __restrict__ xs, const float* __restrict__ W,
                          const float* __restrict__ bias,
                          const float* __restrict__ lg, const float* __restrict__ lb,
                          float* __restrict__ H,
                          __half* __restrict__ Hhi, __half* __restrict__ Hlo)
{
    __shared__ float xv[8];
    __shared__ float red[8];
    const size_t row = blockIdx.x;
    const int tid = threadIdx.x;
    const int c = 2 * tid;
    if (tid < 8) xv[tid] = xs[row * 8 + tid];
    __syncthreads();
    float2 v = *reinterpret_cast<const float2*>(bias + c);
    #pragma unroll
    for (int k = 0; k < 8; k++) {
        float2 w = *reinterpret_cast<const float2*>(W + k * 512 + c);
        v.x = fmaf(xv[k], w.x, v.x);
        v.y = fmaf(xv[k], w.y, v.y);
    }
    const float mean = block_sum512(v.x + v.y, red, tid) * (1.f / 512.f);
    const float d0 = v.x - mean, d1 = v.y - mean;
    const float rstd = rsqrtf(block_sum512(d0 * d0 + d1 * d1, red, tid) * (1.f / 512.f) + 1e-5f);
    const float2 gg = *reinterpret_cast<const float2*>(lg + c);
    const float2 bb = *reinterpret_cast<const float2*>(lb + c);
    float y0 = fmaf(d0 * rstd, gg.x, bb.x);
    float y1 = fmaf(d1 * rstd, gg.y, bb.y);
    y0 = (y0 > 0.f) ? y0 : 0.01f * y0;
    y1 = (y1 > 0.f) ? y1 : 0.01f * y1;
    *reinterpret_cast<float2*>(H + row * 512 + c) = make_float2(y0, y1);
    split_store_pair(Hhi, Hlo, row * 512 + c, y0, y1);
}

// All 16 time-folded W1 biases at once
__global__ void make_bias_all(float* __restrict__ beff, const float* __restrict__ b1,
                              const float* __restrict__ w1_last)
{
    const int i = blockIdx.x * 256 + threadIdx.x;   // < 16*512
    const int idx = i >> 9;
    const int n = i & 511;
    const int s = idx >> 2, st = idx & 3;
    const float toff[4] = {0.f, 0.125f, 0.125f, 0.25f};
    const float tt = (float)s * 0.25f + toff[st];
    beff[i] = fmaf(tt, w1_last[n], b1[n]);
}

// GRU elementwise (torch gate order r,z,n); updates fp32 h + fp16 split
__global__ void gru_step(const float* __restrict__ GI, const float* __restrict__ GH,
                         float* __restrict__ Hs,
                         __half* __restrict__ Shi, __half* __restrict__ Slo)
{
    const int i   = blockIdx.x * blockDim.x + threadIdx.x;
    const int row = i >> 9;
    const int n   = i & 511;
    const float* gi = GI + (size_t)row * 1536;
    const float* gh = GH + (size_t)row * 1536;
    const float r  = 1.f / (1.f + expf(-(gi[n]       + gh[n])));
    const float z  = 1.f / (1.f + expf(-(gi[512 + n] + gh[512 + n])));
    const float nn = tanhf(gi[1024 + n] + r * gh[1024 + n]);
    const float h  = (1.f - z) * nn + z * Hs[i];
    Hs[i] = h;
    split1h(h, Shi[i], Slo[i]);
}

// W[K,N] (fp32 row-major) -> Whi/Wlo[N,K] fp16 split (transposed); Wlo optional
__global__ void wsplit(const float* __restrict__ W,
                       __half* __restrict__ Whi, __half* __restrict__ Wlo,
                       int K, int N)
{
    int idx = blockIdx.x * blockDim.x + threadIdx.x;
    if (idx >= K * N) return;
    int k = idx / N, n = idx % N;
    __half hi, lo;
    split1h(W[idx], hi, lo);
    Whi[(size_t)n * K + k] = hi;
    if (Wlo) Wlo[(size_t)n * K + k] = lo;
}

__global__ void zero_state(float* __restrict__ h,
                           __half* __restrict__ hi, __half* __restrict__ lo)
{
    int i = blockIdx.x * blockDim.x + threadIdx.x;
    h[i] = 0.f;
    hi[i] = __float2half(0.f);
    lo[i] = __float2half(0.f);
}

__global__ void copy_kernel(float* __restrict__ dst, const float* __restrict__ src)
{
    int i = blockIdx.x * blockDim.x + threadIdx.x;
    dst[i] = src[i];
}

// ---------------------------------------------------------------------------
// Launch
// ---------------------------------------------------------------------------
extern "C" void kernel_launch(void* const* d_in, const int* in_sizes, int n_in,
                              void* d_out, int out_size)
{
    const float* xs       = (const float*)d_in[0];
    const float* obs_W    = (const float*)d_in[1];
    const float* obs_b    = (const float*)d_in[2];
    const float* obs_lg   = (const float*)d_in[3];
    const float* obs_lb   = (const float*)d_in[4];
    const float* ode_W1   = (const float*)d_in[5];   // [513, 512]
    const float* ode_b1   = (const float*)d_in[6];
    const float* ln1_g    = (const float*)d_in[7];
    const float* ln1_b    = (const float*)d_in[8];
    const float* ode_W2   = (const float*)d_in[9];
    const float* ode_b2   = (const float*)d_in[10];
    const float* ln2_g    = (const float*)d_in[11];
    const float* ln2_b    = (const float*)d_in[12];
    const float* ode_Wout = (const float*)d_in[13];
    const float* ode_bout = (const float*)d_in[14];
    const float* W_ih     = (const float*)d_in[15];  // [512, 1536]
    const float* b_ih     = (const float*)d_in[16];
    const float* W_hh     = (const float*)d_in[17];
    const float* b_hh     = (const float*)d_in[18];

    float *p_h, *p_acc, *p_z, *p_gi, *p_gh, *p_hst, *p_beff;
    __half *p_hhi, *p_hlo, *p_xhi, *p_yhi, *p_shi, *p_slo;
    __half *w1h, *w2h, *woh, *wih, *wil, *whh, *whl;
    cudaGetSymbolAddress((void**)&p_h,    g_h);
    cudaGetSymbolAddress((void**)&p_acc,  g_acc);
    cudaGetSymbolAddress((void**)&p_z,    g_z);
    cudaGetSymbolAddress((void**)&p_gi,   g_gi);
    cudaGetSymbolAddress((void**)&p_gh,   g_gh);
    cudaGetSymbolAddress((void**)&p_hst,  g_hst);
    cudaGetSymbolAddress((void**)&p_beff, g_beff);
    cudaGetSymbolAddress((void**)&p_hhi,  g_hhi);
    cudaGetSymbolAddress((void**)&p_hlo,  g_hlo);
    cudaGetSymbolAddress((void**)&p_xhi,  g_xhi);
    cudaGetSymbolAddress((void**)&p_yhi,  g_yhi);
    cudaGetSymbolAddress((void**)&p_shi,  g_shi);
    cudaGetSymbolAddress((void**)&p_slo,  g_slo);
    cudaGetSymbolAddress((void**)&w1h,    g_w1hi);
    cudaGetSymbolAddress((void**)&w2h,    g_w2hi);
    cudaGetSymbolAddress((void**)&woh,    g_wohi);
    cudaGetSymbolAddress((void**)&wih,    g_wihi);
    cudaGetSymbolAddress((void**)&wil,    g_wilo);
    cudaGetSymbolAddress((void**)&whh,    g_whhi);
    cudaGetSymbolAddress((void**)&whl,    g_whlo);

    cudaFuncSetAttribute(gemm_f16<128,1>, cudaFuncAttributeMaxDynamicSharedMemorySize, SMEM_P1_128);
    cudaFuncSetAttribute(gemm_f16<128,3>, cudaFuncAttributeMaxDynamicSharedMemorySize, SMEM_P3_128);
    cudaFuncSetAttribute(gemm_f16<64,3>,  cudaFuncAttributeMaxDynamicSharedMemorySize, SMEM_P3_64);
    cudaFuncSetAttribute(gemm_rk4,        cudaFuncAttributeMaxDynamicSharedMemorySize, SMEM_RK4);

    const int M = (int)NROWS;
    __half* nil = nullptr;

    // Weight prep (transpose + fp16 split). W1/W2/Wout need hi only (P1 layers).
    wsplit<<<(512 * 512) / 256, 256>>>(ode_W1,   w1h, nil, 512, 512);
    wsplit<<<(512 * 512) / 256, 256>>>(ode_W2,   w2h, nil, 512, 512);
    wsplit<<<(512 * 512) / 256, 256>>>(ode_Wout, woh, nil, 512, 512);
    wsplit<<<(512 * 1536) / 256, 256>>>(W_ih, wih, wil, 512, 1536);
    wsplit<<<(512 * 1536) / 256, 256>>>(W_hh, whh, whl, 512, 1536);
    make_bias_all<<<32, 256>>>(p_beff, ode_b1, ode_W1 + 512 * 512);

    // obs embedding (ODE initial conditions)
    obs_embed<<<M, 256>>>(xs, obs_W, obs_b, obs_lg, obs_lb, p_h, p_hhi, p_hlo);

    dim3 gBig(512 / 128,  M / 128);       // (4, 512)
    dim3 gGi (1536 / 128, M / 128);       // (12, 512)
    dim3 gGru(1536 / 128, BATCH / 64);    // (12, 16) -> 192 CTAs, now 1 wave
    const int LNG = M / 8;

    // Batched RK4 over ALL timesteps (effective batch 65536)
    for (int s = 0; s < 4; s++) {
        for (int st = 0; st < 4; st++) {
            const float* beff = p_beff + (size_t)(s * 4 + st) * 512;
            const __half* Ah = (st == 0) ? p_hhi : p_yhi;
            gemm_f16<128,1><<<gBig, 256, SMEM_P1_128>>>(Ah, Ah, w1h, w1h, beff, p_z, 512);
            ln_lrelu<<<LNG, 256>>>(p_z, ln1_g, ln1_b, p_xhi);
            gemm_f16<128,1><<<gBig, 256, SMEM_P1_128>>>(p_xhi, p_xhi, w2h, w2h, ode_b2, p_z, 512);
            ln_lrelu<<<LNG, 256>>>(p_z, ln2_g, ln2_b, p_xhi);
            if (st < 3) {
                const float wa = (st == 0) ? 1.f : 2.f;
                const float wy = (st == 2) ? 0.25f : 0.125f;
                gemm_rk4<<<gBig, 256, SMEM_RK4>>>(p_xhi, woh, ode_bout,
                                                  p_h, p_acc, p_yhi, p_hlo,
                                                  wa, wy, (st == 0) ? 0 : 1);
            } else {
                gemm_rk4<<<gBig, 256, SMEM_RK4>>>(p_xhi, woh, ode_bout,
                                                  p_h, p_acc, p_hhi, p_hlo,
                                                  1.f, 0.f, 2);
            }
        }
    }

    // Input gates for all timesteps in one GEMM (P3: near-exact)
    gemm_f16<128,3><<<gGi, 256, SMEM_P3_128>>>(p_hhi, p_hlo, wih, wil, b_ih, p_gi, 1536);

    // Sequential GRU: two-kernel scheme (P3 GEMM now 2 CTAs/SM -> 1 wave)
    zero_state<<<(BATCH * HID) / 256, 256>>>(p_hst, p_shi, p_slo);
    for (int t = 0; t < T_STEPS; t++) {
        gemm_f16<64,3><<<gGru, 256, SMEM_P3_64>>>(p_shi, p_slo, whh, whl, b_hh, p_gh, 1536);
        gru_step<<<(BATCH * HID) / 256, 256>>>(p_gi + (size_t)t * BATCH * G3, p_gh,
                                               p_hst, p_shi, p_slo);
    }

    copy_kernel<<<(BATCH * HID) / 256, 256>>>((float*)d_out, p_hst);
}

// round 15
// speedup vs baseline: 1.8940x; 1.0263x over previous
#include <cuda_runtime.h>
#include <cuda_fp16.h>
#include <cstdint>
#include <cstddef>

// ---------------------------------------------------------------------------
// Dims
// ---------------------------------------------------------------------------
constexpr int    T_STEPS = 64;
constexpr int    BATCH   = 1024;
constexpr int    HID     = 512;
constexpr int    G3      = 3 * HID;                  // 1536
constexpr size_t NROWS   = (size_t)T_STEPS * BATCH;  // 65536
constexpr int    KDIM    = 512;

// ---------------------------------------------------------------------------
// PTX helpers (arch-unconditional, sm_80-era)
// ---------------------------------------------------------------------------
__device__ __forceinline__ uint32_t smem_u32(const void* p) {
    uint32_t a;
    asm("{ .reg .u64 t; cvta.to.shared.u64 t, %1; cvt.u32.u64 %0, t; }"
        : "=r"(a) : "l"(p));
    return a;
}
#define CP16(s, g) \
    asm volatile("cp.async.cg.shared.global [%0], [%1], 16;\n" :: "r"(s), "l"(g) : "memory")
#define CP_COMMIT() asm volatile("cp.async.commit_group;\n" ::: "memory")
#define CP_WAIT_N(n) asm volatile("cp.async.wait_group %0;" :: "n"(n) : "memory")

#define LDM_X4(r, addr)                                                         \
    asm volatile("ldmatrix.sync.aligned.m8n8.x4.shared.b16 {%0,%1,%2,%3}, [%4];" \
        : "=r"((r)[0]), "=r"((r)[1]), "=r"((r)[2]), "=r"((r)[3]) : "r"(addr))

#define MMA_F16(d, a, b0, b1)                                                   \
    asm volatile("mma.sync.aligned.m16n8k16.row.col.f32.f16.f16.f32 "           \
        "{%0,%1,%2,%3}, {%4,%5,%6,%7}, {%8,%9}, {%0,%1,%2,%3};"                 \
        : "+f"((d)[0]), "+f"((d)[1]), "+f"((d)[2]), "+f"((d)[3])                \
        : "r"((a)[0]), "r"((a)[1]), "r"((a)[2]), "r"((a)[3]), "r"(b0), "r"(b1))

// ---------------------------------------------------------------------------
// Scratch
// ---------------------------------------------------------------------------
__device__ float g_h   [NROWS * HID];     // fp32 ODE state
__device__ float g_acc [NROWS * HID];     // RK4 accumulator
__device__ float g_hst [BATCH * HID];
__device__ float g_beff[16 * HID];        // all 16 time-folded W1 biases

__device__ __half g_zh [NROWS * HID];     // fp16 GEMM out (pre-LN)
__device__ __half g_gih[NROWS * G3];      // fp16 input gates
__device__ __half g_ghh[BATCH * G3];      // fp16 hidden gates

__device__ __half g_hhi[NROWS * HID], g_hlo[NROWS * HID];  // h state split
__device__ __half g_xhi[NROWS * HID];                      // LN outputs (hi only)
__device__ __half g_yhi[NROWS * HID];                      // RK4 Y output (hi only)
__device__ __half g_shi[BATCH * HID], g_slo[BATCH * HID];  // GRU state split
__device__ __half g_w1hi[HID * HID];
__device__ __half g_w2hi[HID * HID];
__device__ __half g_wohi[HID * HID];
__device__ __half g_wihi[G3 * HID],   g_wilo[G3 * HID];
__device__ __half g_whhi[G3 * HID],   g_whlo[G3 * HID];

// ---------------------------------------------------------------------------
// fp16 split helpers
// ---------------------------------------------------------------------------
__device__ __forceinline__ void split1h(float v, __half& hi, __half& lo) {
    hi = __float2half(v);
    lo = __float2half(v - __half2float(hi));
}
__device__ __forceinline__ void split_store_pair(__half* Hi, __half* Lo,
                                                 size_t i, float a, float b) {
    __half2 h, l;
    split1h(a, h.x, l.x); split1h(b, h.y, l.y);
    *reinterpret_cast<__half2*>(Hi + i) = h;
    *reinterpret_cast<__half2*>(Lo + i) = l;
}

// ===========================================================================
// fp16 split GEMM: C[M,N] = A @ B^T + bias, B pre-transposed [N,512].
// PRODUCTS==1: C = Ah*Bh.  PRODUCTS==2: + Ah*Bl.  PRODUCTS==3: + Al*Bh.
// OUTH==1: write fp16 output (C cast to __half*), else fp32.
// BM x 128 tile, BK=32, 16 chunks, 256 threads (8 warps 2Mx4N).
// ===========================================================================
template<int BM, int PRODUCTS, int OUTH>
__global__ void __launch_bounds__(256, (PRODUCTS <= 2 || BM == 64) ? 2 : 1)
gemm_f16(const __half* __restrict__ Ahi, const __half* __restrict__ Alo,
         const __half* __restrict__ Bhi, const __half* __restrict__ Blo,
         const float* __restrict__ bias, void* __restrict__ Cv, int N)
{
    constexpr int MF    = BM / 32;
    constexpr int AB    = BM * 64;
    constexpr int ASETS = (PRODUCTS == 3) ? 2 : 1;
    constexpr int BSETS = (PRODUCTS >= 2) ? 2 : 1;
    constexpr int STB   = ASETS * AB + BSETS * 8192;
    constexpr int S     = (PRODUCTS == 3) ? 3 : 4;

    extern __shared__ char smem[];
    const uint32_t sb = smem_u32(smem);
    const int tid  = threadIdx.x;
    const int lane = tid & 31;
    const int wid  = tid >> 5;
    const int wm   = (wid >> 2) * (BM / 2);
    const int wn   = (wid & 3) * 32;
    const size_t bm = (size_t)blockIdx.y * BM;
    const size_t bn = (size_t)blockIdx.x * 128;

    float acc[MF][4][4];
    #pragma unroll
    for (int i = 0; i < MF; i++)
        #pragma unroll
        for (int j = 0; j < 4; j++)
            #pragma unroll
            for (int v = 0; v < 4; v++) acc[i][j][v] = 0.f;

    auto g2s = [&](int kc) {
        const uint32_t st = sb + (uint32_t)(kc % S) * STB;
        const int ko = kc * 32;
        const int c  = tid & 3;
        const int r0 = tid >> 2;
        #pragma unroll
        for (int i = 0; i < BM / 64; i++) {
            const int r = r0 + i * 64;
            const uint32_t sw = (uint32_t)(r * 64 + 16 * (c ^ ((r >> 1) & 3)));
            CP16(st + sw, Ahi + (bm + r) * KDIM + ko + c * 8);
            if constexpr (PRODUCTS == 3)
                CP16(st + AB + sw, Alo + (bm + r) * KDIM + ko + c * 8);
        }
        #pragma unroll
        for (int i = 0; i < 2; i++) {
            const int r = r0 + i * 64;
            const uint32_t sw = (uint32_t)(r * 64 + 16 * (c ^ ((r >> 1) & 3)));
            CP16(st + ASETS * AB + sw, Bhi + (bn + r) * KDIM + ko + c * 8);
            if constexpr (PRODUCTS >= 2)
                CP16(st + ASETS * AB + 8192 + sw, Blo + (bn + r) * KDIM + ko + c * 8);
        }
        CP_COMMIT();
    };

    #pragma unroll
    for (int kc = 0; kc < S - 1; kc++) g2s(kc);

    #pragma unroll 1
    for (int kc = 0; kc < 16; kc++) {
        if constexpr (S == 4) {
            if (kc <= 13) CP_WAIT_N(2);
            else if (kc == 14) CP_WAIT_N(1);
            else CP_WAIT_N(0);
        } else {
            if (kc <= 14) CP_WAIT_N(1);
            else CP_WAIT_N(0);
        }
        __syncthreads();
        if (kc + S - 1 < 16) g2s(kc + S - 1);
        const uint32_t st = sb + (uint32_t)(kc % S) * STB;

        #pragma unroll
        for (int s = 0; s < 2; s++) {
            uint32_t ah[MF][4], al[MF][4], bh[2][4], bl[2][4];
            #pragma unroll
            for (int mf = 0; mf < MF; mf++) {
                const int ar = wm + mf * 16 + (lane & 15);
                const int ac = s * 2 + (lane >> 4);
                const uint32_t sw = (uint32_t)(ar * 64 + 16 * (ac ^ ((ar >> 1) & 3)));
                LDM_X4(ah[mf], st + sw);
                if constexpr (PRODUCTS == 3) LDM_X4(al[mf], st + AB + sw);
            }
            #pragma unroll
            for (int nf16 = 0; nf16 < 2; nf16++) {
                const int br = wn + nf16 * 16 + (lane & 7) + ((lane >> 4) & 1) * 8;
                const int bc = s * 2 + ((lane >> 3) & 1);
                const uint32_t sw = (uint32_t)(br * 64 + 16 * (bc ^ ((br >> 1) & 3)));
                LDM_X4(bh[nf16], st + ASETS * AB + sw);
                if constexpr (PRODUCTS >= 2)
                    LDM_X4(bl[nf16], st + ASETS * AB + 8192 + sw);
            }
            #pragma unroll
            for (int mf = 0; mf < MF; mf++)
                #pragma unroll
                for (int nf = 0; nf < 4; nf++) {
                    const uint32_t b0h = bh[nf >> 1][(nf & 1) * 2];
                    const uint32_t b1h = bh[nf >> 1][(nf & 1) * 2 + 1];
                    MMA_F16(acc[mf][nf], ah[mf], b0h, b1h);
                    if constexpr (PRODUCTS >= 2)
                        MMA_F16(acc[mf][nf], ah[mf],
                                bl[nf >> 1][(nf & 1) * 2], bl[nf >> 1][(nf & 1) * 2 + 1]);
                    if constexpr (PRODUCTS == 3)
                        MMA_F16(acc[mf][nf], al[mf], b0h, b1h);
                }
        }
    }

    #pragma unroll
    for (int mf = 0; mf < MF; mf++) {
        const size_t r0 = bm + wm + mf * 16 + (lane >> 2);
        #pragma unroll
        for (int nf = 0; nf < 4; nf++) {
            const int col = wn + nf * 8 + (lane & 3) * 2;
            const float b0 = bias[bn + col], b1 = bias[bn + col + 1];
            if constexpr (OUTH) {
                __half* Ch = reinterpret_cast<__half*>(Cv);
                *reinterpret_cast<__half2*>(Ch + r0 * N + bn + col) =
                    __floats2half2_rn(acc[mf][nf][0] + b0, acc[mf][nf][1] + b1);
                *reinterpret_cast<__half2*>(Ch + (r0 + 8) * N + bn + col) =
                    __floats2half2_rn(acc[mf][nf][2] + b0, acc[mf][nf][3] + b1);
            } else {
                float* C = reinterpret_cast<float*>(Cv);
                *reinterpret_cast<float2*>(C + r0 * N + bn + col) =
                    make_float2(acc[mf][nf][0] + b0, acc[mf][nf][1] + b1);
                *reinterpret_cast<float2*>(C + (r0 + 8) * N + bn + col) =
                    make_float2(acc[mf][nf][2] + b0, acc[mf][nf][3] + b1);
            }
        }
    }
}

constexpr int SMEM_P1_128 = 4 * (128 * 64 + 8192);        // 65536
constexpr int SMEM_P3_128 = 3 * (2 * 128 * 64 + 16384);   // 98304
constexpr int SMEM_P3_64  = 3 * (2 * 64 * 64 + 16384);    // 73728
constexpr int SMEM_RK4    = 4 * (128 * 64 + 8192);        // 65536 (P1)

// ===========================================================================
// Wout GEMM (P1: Ah*Bh only, BM=128, N=512) + RK4 epilogue.
// mode0: Acc=K, Y=H+wy*K -> Yhi.  mode1: Acc+=wacc*K, Y -> Yhi.
// mode2: H+=(Acc+K)/24 -> H fp32, Yhi=hi(H), Hlo2=lo(H).
// ===========================================================================
__global__ void __launch_bounds__(256, 2)
gemm_rk4(const __half* __restrict__ Ahi,
         const __half* __restrict__ Bhi,
         const float* __restrict__ bias,
         float* __restrict__ H, float* __restrict__ Acc,
         __half* __restrict__ Yhi, __half* __restrict__ Hlo2,
         float wacc, float wy, int mode)
{
    constexpr int AB  = 128 * 64;
    constexpr int STB = AB + 8192;      // 16384
    extern __shared__ char smem[];
    const uint32_t sb = smem_u32(smem);
    const int tid  = threadIdx.x;
    const int lane = tid & 31;
    const int wid  = tid >> 5;
    const int wm   = (wid >> 2) * 64;
    const int wn   = (wid & 3) * 32;
    const size_t bm = (size_t)blockIdx.y * 128;
    const size_t bn = (size_t)blockIdx.x * 128;

    float acc[4][4][4];
    #pragma unroll
    for (int i = 0; i < 4; i++)
        #pragma unroll
        for (int j = 0; j < 4; j++)
            #pragma unroll
            for (int v = 0; v < 4; v++) acc[i][j][v] = 0.f;

    auto g2s = [&](int kc) {
        const uint32_t st = sb + (uint32_t)(kc & 3) * STB;
        const int ko = kc * 32;
        const int c  = tid & 3;
        const int r0 = tid >> 2;
        #pragma unroll
        for (int i = 0; i < 2; i++) {
            const int r = r0 + i * 64;
            const uint32_t sw = (uint32_t)(r * 64 + 16 * (c ^ ((r >> 1) & 3)));
            CP16(st + sw,      Ahi + (bm + r) * KDIM + ko + c * 8);
            CP16(st + AB + sw, Bhi + (bn + r) * KDIM + ko + c * 8);
        }
        CP_COMMIT();
    };

    #pragma unroll
    for (int kc = 0; kc < 3; kc++) g2s(kc);

    #pragma unroll 1
    for (int kc = 0; kc < 16; kc++) {
        if (kc <= 13) CP_WAIT_N(2);
        else if (kc == 14) CP_WAIT_N(1);
        else CP_WAIT_N(0);
        __syncthreads();
        if (kc + 3 < 16) g2s(kc + 3);
        const uint32_t st = sb + (uint32_t)(kc & 3) * STB;

        #pragma unroll
        for (int s = 0; s < 2; s++) {
            uint32_t ah[4][4], bh[2][4];
            #pragma unroll
            for (int mf = 0; mf < 4; mf++) {
                const int ar = wm + mf * 16 + (lane & 15);
                const int ac = s * 2 + (lane >> 4);
                LDM_X4(ah[mf], st + (uint32_t)(ar * 64 + 16 * (ac ^ ((ar >> 1) & 3))));
            }
            #pragma unroll
            for (int nf16 = 0; nf16 < 2; nf16++) {
                const int br = wn + nf16 * 16 + (lane & 7) + ((lane >> 4) & 1) * 8;
                const int bc = s * 2 + ((lane >> 3) & 1);
                LDM_X4(bh[nf16], st + AB + (uint32_t)(br * 64 + 16 * (bc ^ ((br >> 1) & 3))));
            }
            #pragma unroll
            for (int mf = 0; mf < 4; mf++)
                #pragma unroll
                for (int nf = 0; nf < 4; nf++)
                    MMA_F16(acc[mf][nf], ah[mf],
                            bh[nf >> 1][(nf & 1) * 2], bh[nf >> 1][(nf & 1) * 2 + 1]);
        }
    }

    // RK4 epilogue
    #pragma unroll
    for (int mf = 0; mf < 4; mf++)
        #pragma unroll
        for (int nf = 0; nf < 4; nf++) {
            const int col = wn + nf * 8 + 2 * (lane & 3);
            const float b0 = bias[bn + col], b1 = bias[bn + col + 1];
            #pragma unroll
            for (int hv = 0; hv < 2; hv++) {
                const size_t row = bm + wm + mf * 16 + (lane >> 2) + 8 * hv;
                const size_t ix = row * 512 + bn + col;
                const float k0 = acc[mf][nf][2 * hv]     + b0;
                const float k1 = acc[mf][nf][2 * hv + 1] + b1;
                if (mode == 0) {
                    *reinterpret_cast<float2*>(Acc + ix) = make_float2(k0, k1);
                    const float2 h2 = *reinterpret_cast<const float2*>(H + ix);
                    *reinterpret_cast<__half2*>(Yhi + ix) =
                        __floats2half2_rn(fmaf(wy, k0, h2.x), fmaf(wy, k1, h2.y));
                } else if (mode == 1) {
                    float2 a2 = *reinterpret_cast<const float2*>(Acc + ix);
                    a2.x = fmaf(wacc, k0, a2.x); a2.y = fmaf(wacc, k1, a2.y);
                    *reinterpret_cast<float2*>(Acc + ix) = a2;
                    const float2 h2 = *reinterpret_cast<const float2*>(H + ix);
                    *reinterpret_cast<__half2*>(Yhi + ix) =
                        __floats2half2_rn(fmaf(wy, k0, h2.x), fmaf(wy, k1, h2.y));
                } else {
                    const float2 a2 = *reinterpret_cast<const float2*>(Acc + ix);
                    float2 h2 = *reinterpret_cast<const float2*>(H + ix);
                    const float cc = 1.0f / 24.0f;
                    h2.x = fmaf(a2.x + k0, cc, h2.x);
                    h2.y = fmaf(a2.y + k1, cc, h2.y);
                    *reinterpret_cast<float2*>(H + ix) = h2;
                    split_store_pair(Yhi, Hlo2, ix, h2.x, h2.y);
                }
            }
        }
}

// ---------------------------------------------------------------------------
// LayerNorm(512)+LeakyReLU, warp-per-row. fp16 in -> fp16 HI only.
// ---------------------------------------------------------------------------
__global__ void ln_lrelu(const __half* __restrict__ Z,
                         const float* __restrict__ g, const float* __restrict__ b,
                         __half* __restrict__ Xhi)
{
    const int lane = threadIdx.x & 31;
    const size_t row = (size_t)blockIdx.x * 8 + (threadIdx.x >> 5);
    const __half* z = Z + row * 512;

    float4 v[4];
    #pragma unroll
    for (int i = 0; i < 4; i++) {
        uint2 raw = *reinterpret_cast<const uint2*>(z + i * 128 + lane * 4);
        const float2 f0 = __half22float2(*reinterpret_cast<__half2*>(&raw.x));
        const float2 f1 = __half22float2(*reinterpret_cast<__half2*>(&raw.y));
        v[i] = make_float4(f0.x, f0.y, f1.x, f1.y);
    }

    float s = 0.f;
    #pragma unroll
    for (int i = 0; i < 4; i++) s += v[i].x + v[i].y + v[i].z + v[i].w;
    #pragma unroll
    for (int o = 16; o > 0; o >>= 1) s += __shfl_xor_sync(0xffffffffu, s, o);
    const float mean = s * (1.0f / 512.0f);

    float q = 0.f;
    #pragma unroll
    for (int i = 0; i < 4; i++) {
        const float d0 = v[i].x - mean, d1 = v[i].y - mean;
        const float d2 = v[i].z - mean, d3 = v[i].w - mean;
        q += d0 * d0 + d1 * d1 + d2 * d2 + d3 * d3;
    }
    #pragma unroll
    for (int o = 16; o > 0; o >>= 1) q += __shfl_xor_sync(0xffffffffu, q, o);
    const float rstd = rsqrtf(q * (1.0f / 512.0f) + 1e-5f);

    #pragma unroll
    for (int i = 0; i < 4; i++) {
        const int c = i * 128 + lane * 4;
        const float4 gg = *reinterpret_cast<const float4*>(g + c);
        const float4 bb = *reinterpret_cast<const float4*>(b + c);
        float y0 = fmaf((v[i].x - mean) * rstd, gg.x, bb.x);
        float y1 = fmaf((v[i].y - mean) * rstd, gg.y, bb.y);
        float y2 = fmaf((v[i].z - mean) * rstd, gg.z, bb.z);
        float y3 = fmaf((v[i].w - mean) * rstd, gg.w, bb.w);
        y0 = (y0 > 0.f) ? y0 : 0.01f * y0;
        y1 = (y1 > 0.f) ? y1 : 0.01f * y1;
        y2 = (y2 > 0.f) ? y2 : 0.01f * y2;
        y3 = (y3 > 0.f) ? y3 : 0.01f * y3;
        *reinterpret_cast<__half2*>(Xhi + row * 512 + c)     = __floats2half2_rn(y0, y1);
        *reinterpret_cast<__half2*>(Xhi + row * 512 + c + 2) = __floats2half2_rn(y2, y3);
    }
}

// ---------------------------------------------------------------------------
// obs -> hidden: Linear(8->512)+LN+LeakyReLU; fp32 H + fp16 split
// ---------------------------------------------------------------------------
__device__ __forceinline__ float block_sum512(float x, float* red, int tid) {
    #pragma unroll
    for (int o = 16; o > 0; o >>= 1) x += __shfl_xor_sync(0xffffffffu, x, o);
    __syncthreads();
    if ((tid & 31) == 0) red[tid >> 5] = x;
    __syncthreads();
    float t = 0.f;
    #pragma unroll
    for (int i = 0; i < 8; i++) t += red[i];
    return t;
}

__global__ void obs_embed(const float* __restrict__ xs, const float* __restrict__ W,
                          const float* __restrict__ bias,
                          const float* __restrict__ lg, const float* __restrict__ lb,
                          float* __restrict__ H,
                          __half* __restrict__ Hhi, __half* __restrict__ Hlo)
{
    __shared__ float xv[8];
    __shared__ float red[8];
    const size_t row = blockIdx.x;
    const int tid = threadIdx.x;
    const int c = 2 * tid;
    if (tid < 8) xv[tid] = xs[row * 8 + tid];
    __syncthreads();
    float2 v = *reinterpret_cast<const float2*>(bias + c);
    #pragma unroll
    for (int k = 0; k < 8; k++) {
        float2 w = *reinterpret_cast<const float2*>(W + k * 512 + c);
        v.x = fmaf(xv[k], w.x, v.x);
        v.y = fmaf(xv[k], w.y, v.y);
    }
    const float mean = block_sum512(v.x + v.y, red, tid) * (1.f / 512.f);
    const float d0 = v.x - mean, d1 = v.y - mean;
    const float rstd = rsqrtf(block_sum512(d0 * d0 + d1 * d1, red, tid) * (1.f / 512.f) + 1e-5f);
    const float2 gg = *reinterpret_cast<const float2*>(lg + c);
    const float2 bb = *reinterpret_cast<const float2*>(lb + c);
    float y0 = fmaf(d0 * rstd, gg.x, bb.x);
    float y1 = fmaf(d1 * rstd, gg.y, bb.y);
    y0 = (y0 > 0.f) ? y0 : 0.01f * y0;
    y1 = (y1 > 0.f) ? y1 : 0.01f * y1;
    *reinterpret_cast<float2*>(H + row * 512 + c) = make_float2(y0, y1);
    split_store_pair(Hhi, Hlo, row * 512 + c, y0, y1);
}

// All 16 time-folded W1 biases at once
__global__ void make_bias_all(float* __restrict__ beff, const float* __restrict__ b1,
                              const float* __restrict__ w1_last)
{
    const int i = blockIdx.x * 256 + threadIdx.x;   // < 16*512
    const int idx = i >> 9;
    const int n = i & 511;
    const int s = idx >> 2, st = idx & 3;
    const float toff[4] = {0.f, 0.125f, 0.125f, 0.25f};
    const float tt = (float)s * 0.25f + toff[st];
    beff[i] = fmaf(tt, w1_last[n], b1[n]);
}

// GRU elementwise (torch gate order r,z,n); fp16 gate inputs, fp32 h + fp16 split
__global__ void gru_step(const __half* __restrict__ GI, const __half* __restrict__ GH,
                         float* __restrict__ Hs,
                         __half* __restrict__ Shi, __half* __restrict__ Slo)
{
    const int i   = blockIdx.x * blockDim.x + threadIdx.x;
    const int row = i >> 9;
    const int n   = i & 511;
    const __half* gi = GI + (size_t)row * 1536;
    const __half* gh = GH + (size_t)row * 1536;
    const float r  = 1.f / (1.f + expf(-(__half2float(gi[n])        + __half2float(gh[n]))));
    const float z  = 1.f / (1.f + expf(-(__half2float(gi[512 + n])  + __half2float(gh[512 + n]))));
    const float nn = tanhf(__half2float(gi[1024 + n]) + r * __half2float(gh[1024 + n]));
    const float h  = (1.f - z) * nn + z * Hs[i];
    Hs[i] = h;
    split1h(h, Shi[i], Slo[i]);
}

// W[K,N] (fp32 row-major) -> Whi/Wlo[N,K] fp16 split (transposed); Wlo optional
__global__ void wsplit(const float* __restrict__ W,
                       __half* __restrict__ Whi, __half* __restrict__ Wlo,
                       int K, int N)
{
    int idx = blockIdx.x * blockDim.x + threadIdx.x;
    if (idx >= K * N) return;
    int k = idx / N, n = idx % N;
    __half hi, lo;
    split1h(W[idx], hi, lo);
    Whi[(size_t)n * K + k] = hi;
    if (Wlo) Wlo[(size_t)n * K + k] = lo;
}

__global__ void zero_state(float* __restrict__ h,
                           __half* __restrict__ hi, __half* __restrict__ lo)
{
    int i = blockIdx.x * blockDim.x + threadIdx.x;
    h[i] = 0.f;
    hi[i] = __float2half(0.f);
    lo[i] = __float2half(0.f);
}

__global__ void copy_kernel(float* __restrict__ dst, const float* __restrict__ src)
{
    int i = blockIdx.x * blockDim.x + threadIdx.x;
    dst[i] = src[i];
}

// ---------------------------------------------------------------------------
// Launch
// ---------------------------------------------------------------------------
extern "C" void kernel_launch(void* const* d_in, const int* in_sizes, int n_in,
                              void* d_out, int out_size)
{
    const float* xs       = (const float*)d_in[0];
    const float* obs_W    = (const float*)d_in[1];
    const float* obs_b    = (const float*)d_in[2];
    const float* obs_lg   = (const float*)d_in[3];
    const float* obs_lb   = (const float*)d_in[4];
    const float* ode_W1   = (const float*)d_in[5];   // [513, 512]
    const float* ode_b1   = (const float*)d_in[6];
    const float* ln1_g    = (const float*)d_in[7];
    const float* ln1_b    = (const float*)d_in[8];
    const float* ode_W2   = (const float*)d_in[9];
    const float* ode_b2   = (const float*)d_in[10];
    const float* ln2_g    = (const float*)d_in[11];
    const float* ln2_b    = (const float*)d_in[12];
    const float* ode_Wout = (const float*)d_in[13];
    const float* ode_bout = (const float*)d_in[14];
    const float* W_ih     = (const float*)d_in[15];  // [512, 1536]
    const float* b_ih     = (const float*)d_in[16];
    const float* W_hh     = (const float*)d_in[17];
    const float* b_hh     = (const float*)d_in[18];

    float *p_h, *p_acc, *p_hst, *p_beff;
    __half *p_zh, *p_gih, *p_ghh;
    __half *p_hhi, *p_hlo, *p_xhi, *p_yhi, *p_shi, *p_slo;
    __half *w1h, *w2h, *woh, *wih, *wil, *whh, *whl;
    cudaGetSymbolAddress((void**)&p_h,    g_h);
    cudaGetSymbolAddress((void**)&p_acc,  g_acc);
    cudaGetSymbolAddress((void**)&p_hst,  g_hst);
    cudaGetSymbolAddress((void**)&p_beff, g_beff);
    cudaGetSymbolAddress((void**)&p_zh,   g_zh);
    cudaGetSymbolAddress((void**)&p_gih,  g_gih);
    cudaGetSymbolAddress((void**)&p_ghh,  g_ghh);
    cudaGetSymbolAddress((void**)&p_hhi,  g_hhi);
    cudaGetSymbolAddress((void**)&p_hlo,  g_hlo);
    cudaGetSymbolAddress((void**)&p_xhi,  g_xhi);
    cudaGetSymbolAddress((void**)&p_yhi,  g_yhi);
    cudaGetSymbolAddress((void**)&p_shi,  g_shi);
    cudaGetSymbolAddress((void**)&p_slo,  g_slo);
    cudaGetSymbolAddress((void**)&w1h,    g_w1hi);
    cudaGetSymbolAddress((void**)&w2h,    g_w2hi);
    cudaGetSymbolAddress((void**)&woh,    g_wohi);
    cudaGetSymbolAddress((void**)&wih,    g_wihi);
    cudaGetSymbolAddress((void**)&wil,    g_wilo);
    cudaGetSymbolAddress((void**)&whh,    g_whhi);
    cudaGetSymbolAddress((void**)&whl,    g_whlo);

    cudaFuncSetAttribute(gemm_f16<128,1,1>, cudaFuncAttributeMaxDynamicSharedMemorySize, SMEM_P1_128);
    cudaFuncSetAttribute(gemm_f16<128,3,1>, cudaFuncAttributeMaxDynamicSharedMemorySize, SMEM_P3_128);
    cudaFuncSetAttribute(gemm_f16<64,3,1>,  cudaFuncAttributeMaxDynamicSharedMemorySize, SMEM_P3_64);
    cudaFuncSetAttribute(gemm_rk4,          cudaFuncAttributeMaxDynamicSharedMemorySize, SMEM_RK4);

    const int M = (int)NROWS;
    __half* nil = nullptr;

    // Weight prep (transpose + fp16 split). W1/W2/Wout need hi only (P1 layers).
    wsplit<<<(512 * 512) / 256, 256>>>(ode_W1,   w1h, nil, 512, 512);
    wsplit<<<(512 * 512) / 256, 256>>>(ode_W2,   w2h, nil, 512, 512);
    wsplit<<<(512 * 512) / 256, 256>>>(ode_Wout, woh, nil, 512, 512);
    wsplit<<<(512 * 1536) / 256, 256>>>(W_ih, wih, wil, 512, 1536);
    wsplit<<<(512 * 1536) / 256, 256>>>(W_hh, whh, whl, 512, 1536);
    make_bias_all<<<32, 256>>>(p_beff, ode_b1, ode_W1 + 512 * 512);

    // obs embedding (ODE initial conditions)
    obs_embed<<<M, 256>>>(xs, obs_W, obs_b, obs_lg, obs_lb, p_h, p_hhi, p_hlo);

    dim3 gBig(512 / 128,  M / 128);       // (4, 512)
    dim3 gGi (1536 / 128, M / 128);       // (12, 512)
    dim3 gGru(1536 / 128, BATCH / 64);    // (12, 16) -> 192 CTAs, 1 wave
    const int LNG = M / 8;

    // Batched RK4 over ALL timesteps (effective batch 65536)
    for (int s = 0; s < 4; s++) {
        for (int st = 0; st < 4; st++) {
            const float* beff = p_beff + (size_t)(s * 4 + st) * 512;
            const __half* Ah = (st == 0) ? p_hhi : p_yhi;
            gemm_f16<128,1,1><<<gBig, 256, SMEM_P1_128>>>(Ah, Ah, w1h, w1h, beff, p_zh, 512);
            ln_lrelu<<<LNG, 256>>>(p_zh, ln1_g, ln1_b, p_xhi);
            gemm_f16<128,1,1><<<gBig, 256, SMEM_P1_128>>>(p_xhi, p_xhi, w2h, w2h, ode_b2, p_zh, 512);
            ln_lrelu<<<LNG, 256>>>(p_zh, ln2_g, ln2_b, p_xhi);
            if (st < 3) {
                const float wa = (st == 0) ? 1.f : 2.f;
                const float wy = (st == 2) ? 0.25f : 0.125f;
                gemm_rk4<<<gBig, 256, SMEM_RK4>>>(p_xhi, woh, ode_bout,
                                                  p_h, p_acc, p_yhi, p_hlo,
                                                  wa, wy, (st == 0) ? 0 : 1);
            } else {
                gemm_rk4<<<gBig, 256, SMEM_RK4>>>(p_xhi, woh, ode_bout,
                                                  p_h, p_acc, p_hhi, p_hlo,
                                                  1.f, 0.f, 2);
            }
        }
    }

    // Input gates for all timesteps in one GEMM (P3, fp16 out)
    gemm_f16<128,3,1><<<gGi, 256, SMEM_P3_128>>>(p_hhi, p_hlo, wih, wil, b_ih, p_gih, 1536);

    // Sequential GRU: two-kernel scheme (P3 GEMM, fp16 gh out, 2 CTAs/SM)
    zero_state<<<(BATCH * HID) / 256, 256>>>(p_hst, p_shi, p_slo);
    for (int t = 0; t < T_STEPS; t++) {
        gemm_f16<64,3,1><<<gGru, 256, SMEM_P3_64>>>(p_shi, p_slo, whh, whl, b_hh, p_ghh, 1536);
        gru_step<<<(BATCH * HID) / 256, 256>>>(p_gih + (size_t)t * BATCH * G3, p_ghh,
                                               p_hst, p_shi, p_slo);
    }

    copy_kernel<<<(BATCH * HID) / 256, 256>>>((float*)d_out, p_hst);
}

// round 16
// speedup vs baseline: 2.0147x; 1.0638x over previous
#include <cuda_runtime.h>
#include <cuda_fp16.h>
#include <cstdint>
#include <cstddef>

// ---------------------------------------------------------------------------
// Dims
// ---------------------------------------------------------------------------
constexpr int    T_STEPS = 64;
constexpr int    BATCH   = 1024;
constexpr int    HID     = 512;
constexpr int    G3      = 3 * HID;                  // 1536
constexpr size_t NROWS   = (size_t)T_STEPS * BATCH;  // 65536
constexpr int    KDIM    = 512;

// ---------------------------------------------------------------------------
// PTX helpers (arch-unconditional, sm_80-era)
// ---------------------------------------------------------------------------
__device__ __forceinline__ uint32_t smem_u32(const void* p) {
    uint32_t a;
    asm("{ .reg .u64 t; cvta.to.shared.u64 t, %1; cvt.u32.u64 %0, t; }"
        : "=r"(a) : "l"(p));
    return a;
}
#define CP16(s, g) \
    asm volatile("cp.async.cg.shared.global [%0], [%1], 16;\n" :: "r"(s), "l"(g) : "memory")
#define CP_COMMIT() asm volatile("cp.async.commit_group;\n" ::: "memory")
#define CP_WAIT_N(n) asm volatile("cp.async.wait_group %0;" :: "n"(n) : "memory")

#define LDM_X4(r, addr)                                                         \
    asm volatile("ldmatrix.sync.aligned.m8n8.x4.shared.b16 {%0,%1,%2,%3}, [%4];" \
        : "=r"((r)[0]), "=r"((r)[1]), "=r"((r)[2]), "=r"((r)[3]) : "r"(addr))

#define MMA_F16(d, a, b0, b1)                                                   \
    asm volatile("mma.sync.aligned.m16n8k16.row.col.f32.f16.f16.f32 "           \
        "{%0,%1,%2,%3}, {%4,%5,%6,%7}, {%8,%9}, {%0,%1,%2,%3};"                 \
        : "+f"((d)[0]), "+f"((d)[1]), "+f"((d)[2]), "+f"((d)[3])                \
        : "r"((a)[0]), "r"((a)[1]), "r"((a)[2]), "r"((a)[3]), "r"(b0), "r"(b1))

// ---------------------------------------------------------------------------
// Scratch
// ---------------------------------------------------------------------------
__device__ float g_h   [NROWS * HID];     // fp32 ODE state
__device__ float g_acc [NROWS * HID];     // RK4 accumulator
__device__ float g_hst [BATCH * HID];
__device__ float g_beff[16 * HID];        // all 16 time-folded W1 biases

__device__ __half g_zh [NROWS * HID];     // fp16 GEMM out (pre-LN)
__device__ __half g_gih[NROWS * G3];      // fp16 input gates
__device__ __half g_ghh[BATCH * G3];      // fp16 hidden gates

__device__ __half g_hhi[NROWS * HID], g_hlo[NROWS * HID];  // h state split
__device__ __half g_xhi[NROWS * HID];                      // LN outputs (hi only)
__device__ __half g_yhi[NROWS * HID];                      // RK4 Y output (hi only)
__device__ __half g_shi[BATCH * HID], g_slo[BATCH * HID];  // GRU state split
__device__ __half g_w1hi[HID * HID];
__device__ __half g_w2hi[HID * HID];
__device__ __half g_wohi[HID * HID];
__device__ __half g_wihi[G3 * HID],   g_wilo[G3 * HID];
__device__ __half g_whhi[G3 * HID],   g_whlo[G3 * HID];

// ---------------------------------------------------------------------------
// fp16 split helpers
// ---------------------------------------------------------------------------
__device__ __forceinline__ void split1h(float v, __half& hi, __half& lo) {
    hi = __float2half(v);
    lo = __float2half(v - __half2float(hi));
}
__device__ __forceinline__ void split_store_pair(__half* Hi, __half* Lo,
                                                 size_t i, float a, float b) {
    __half2 h, l;
    split1h(a, h.x, l.x); split1h(b, h.y, l.y);
    *reinterpret_cast<__half2*>(Hi + i) = h;
    *reinterpret_cast<__half2*>(Lo + i) = l;
}

// ===========================================================================
// fp16 split GEMM: C[M,N] = A @ B^T + bias, B pre-transposed [N,512].
// PRODUCTS==1: C = Ah*Bh.  PRODUCTS==2: + Ah*Bl.  PRODUCTS==3: + Al*Bh.
// OUTH==1: fp16 output.  Stages: P1=6, P2=4, P3=3.
// BM x 128 tile, BK=32, 16 chunks, 256 threads (8 warps 2Mx4N).
// ===========================================================================
template<int BM, int PRODUCTS, int OUTH>
__global__ void __launch_bounds__(256, (PRODUCTS <= 2 || BM == 64) ? 2 : 1)
gemm_f16(const __half* __restrict__ Ahi, const __half* __restrict__ Alo,
         const __half* __restrict__ Bhi, const __half* __restrict__ Blo,
         const float* __restrict__ bias, void* __restrict__ Cv, int N)
{
    constexpr int MF    = BM / 32;
    constexpr int AB    = BM * 64;
    constexpr int ASETS = (PRODUCTS == 3) ? 2 : 1;
    constexpr int BSETS = (PRODUCTS >= 2) ? 2 : 1;
    constexpr int STB   = ASETS * AB + BSETS * 8192;
    constexpr int S     = (PRODUCTS == 3) ? 3 : ((PRODUCTS == 1) ? 6 : 4);

    extern __shared__ char smem[];
    const uint32_t sb = smem_u32(smem);
    const int tid  = threadIdx.x;
    const int lane = tid & 31;
    const int wid  = tid >> 5;
    const int wm   = (wid >> 2) * (BM / 2);
    const int wn   = (wid & 3) * 32;
    const size_t bm = (size_t)blockIdx.y * BM;
    const size_t bn = (size_t)blockIdx.x * 128;

    float acc[MF][4][4];
    #pragma unroll
    for (int i = 0; i < MF; i++)
        #pragma unroll
        for (int j = 0; j < 4; j++)
            #pragma unroll
            for (int v = 0; v < 4; v++) acc[i][j][v] = 0.f;

    auto g2s = [&](int kc) {
        const uint32_t st = sb + (uint32_t)(kc % S) * STB;
        const int ko = kc * 32;
        const int c  = tid & 3;
        const int r0 = tid >> 2;
        #pragma unroll
        for (int i = 0; i < BM / 64; i++) {
            const int r = r0 + i * 64;
            const uint32_t sw = (uint32_t)(r * 64 + 16 * (c ^ ((r >> 1) & 3)));
            CP16(st + sw, Ahi + (bm + r) * KDIM + ko + c * 8);
            if constexpr (PRODUCTS == 3)
                CP16(st + AB + sw, Alo + (bm + r) * KDIM + ko + c * 8);
        }
        #pragma unroll
        for (int i = 0; i < 2; i++) {
            const int r = r0 + i * 64;
            const uint32_t sw = (uint32_t)(r * 64 + 16 * (c ^ ((r >> 1) & 3)));
            CP16(st + ASETS * AB + sw, Bhi + (bn + r) * KDIM + ko + c * 8);
            if constexpr (PRODUCTS >= 2)
                CP16(st + ASETS * AB + 8192 + sw, Blo + (bn + r) * KDIM + ko + c * 8);
        }
        CP_COMMIT();
    };

    #pragma unroll
    for (int kc = 0; kc < S - 1; kc++) g2s(kc);

    #pragma unroll 1
    for (int kc = 0; kc < 16; kc++) {
        // group kc must be complete after this wait
        if (kc <= 16 - (S - 1)) CP_WAIT_N(S - 2);
        else if (kc == 12)      CP_WAIT_N(3);
        else if (kc == 13)      CP_WAIT_N(2);
        else if (kc == 14)      CP_WAIT_N(1);
        else                    CP_WAIT_N(0);
        __syncthreads();
        if (kc + S - 1 < 16) g2s(kc + S - 1);
        const uint32_t st = sb + (uint32_t)(kc % S) * STB;

        #pragma unroll
        for (int s = 0; s < 2; s++) {
            uint32_t ah[MF][4], al[MF][4], bh[2][4], bl[2][4];
            #pragma unroll
            for (int mf = 0; mf < MF; mf++) {
                const int ar = wm + mf * 16 + (lane & 15);
                const int ac = s * 2 + (lane >> 4);
                const uint32_t sw = (uint32_t)(ar * 64 + 16 * (ac ^ ((ar >> 1) & 3)));
                LDM_X4(ah[mf], st + sw);
                if constexpr (PRODUCTS == 3) LDM_X4(al[mf], st + AB + sw);
            }
            #pragma unroll
            for (int nf16 = 0; nf16 < 2; nf16++) {
                const int br = wn + nf16 * 16 + (lane & 7) + ((lane >> 4) & 1) * 8;
                const int bc = s * 2 + ((lane >> 3) & 1);
                const uint32_t sw = (uint32_t)(br * 64 + 16 * (bc ^ ((br >> 1) & 3)));
                LDM_X4(bh[nf16], st + ASETS * AB + sw);
                if constexpr (PRODUCTS >= 2)
                    LDM_X4(bl[nf16], st + ASETS * AB + 8192 + sw);
            }
            #pragma unroll
            for (int mf = 0; mf < MF; mf++)
                #pragma unroll
                for (int nf = 0; nf < 4; nf++) {
                    const uint32_t b0h = bh[nf >> 1][(nf & 1) * 2];
                    const uint32_t b1h = bh[nf >> 1][(nf & 1) * 2 + 1];
                    MMA_F16(acc[mf][nf], ah[mf], b0h, b1h);
                    if constexpr (PRODUCTS >= 2)
                        MMA_F16(acc[mf][nf], ah[mf],
                                bl[nf >> 1][(nf & 1) * 2], bl[nf >> 1][(nf & 1) * 2 + 1]);
                    if constexpr (PRODUCTS == 3)
                        MMA_F16(acc[mf][nf], al[mf], b0h, b1h);
                }
        }
    }

    #pragma unroll
    for (int mf = 0; mf < MF; mf++) {
        const size_t r0 = bm + wm + mf * 16 + (lane >> 2);
        #pragma unroll
        for (int nf = 0; nf < 4; nf++) {
            const int col = wn + nf * 8 + (lane & 3) * 2;
            const float b0 = bias[bn + col], b1 = bias[bn + col + 1];
            if constexpr (OUTH) {
                __half* Ch = reinterpret_cast<__half*>(Cv);
                *reinterpret_cast<__half2*>(Ch + r0 * N + bn + col) =
                    __floats2half2_rn(acc[mf][nf][0] + b0, acc[mf][nf][1] + b1);
                *reinterpret_cast<__half2*>(Ch + (r0 + 8) * N + bn + col) =
                    __floats2half2_rn(acc[mf][nf][2] + b0, acc[mf][nf][3] + b1);
            } else {
                float* C = reinterpret_cast<float*>(Cv);
                *reinterpret_cast<float2*>(C + r0 * N + bn + col) =
                    make_float2(acc[mf][nf][0] + b0, acc[mf][nf][1] + b1);
                *reinterpret_cast<float2*>(C + (r0 + 8) * N + bn + col) =
                    make_float2(acc[mf][nf][2] + b0, acc[mf][nf][3] + b1);
            }
        }
    }
}

constexpr int SMEM_P1_128 = 6 * (128 * 64 + 8192);        // 98304 (S=6)
constexpr int SMEM_P2_128 = 4 * (128 * 64 + 16384);       // 98304
constexpr int SMEM_P2_64  = 4 * (64 * 64 + 16384);        // 81920
constexpr int SMEM_RK4    = 4 * (128 * 64 + 8192);        // 65536 (P1, S=4)

// ===========================================================================
// Wout GEMM (P1: Ah*Bh only, BM=128, N=512) + RK4 epilogue.
// mode0: Acc=K, Y=H+wy*K -> Yhi.  mode1: Acc+=wacc*K, Y -> Yhi.
// mode2: H+=(Acc+K)/24 -> H fp32, Yhi=hi(H), Hlo2=lo(H).
// ===========================================================================
__global__ void __launch_bounds__(256, 2)
gemm_rk4(const __half* __restrict__ Ahi,
         const __half* __restrict__ Bhi,
         const float* __restrict__ bias,
         float* __restrict__ H, float* __restrict__ Acc,
         __half* __restrict__ Yhi, __half* __restrict__ Hlo2,
         float wacc, float wy, int mode)
{
    constexpr int AB  = 128 * 64;
    constexpr int STB = AB + 8192;      // 16384
    extern __shared__ char smem[];
    const uint32_t sb = smem_u32(smem);
    const int tid  = threadIdx.x;
    const int lane = tid & 31;
    const int wid  = tid >> 5;
    const int wm   = (wid >> 2) * 64;
    const int wn   = (wid & 3) * 32;
    const size_t bm = (size_t)blockIdx.y * 128;
    const size_t bn = (size_t)blockIdx.x * 128;

    float acc[4][4][4];
    #pragma unroll
    for (int i = 0; i < 4; i++)
        #pragma unroll
        for (int j = 0; j < 4; j++)
            #pragma unroll
            for (int v = 0; v < 4; v++) acc[i][j][v] = 0.f;

    auto g2s = [&](int kc) {
        const uint32_t st = sb + (uint32_t)(kc & 3) * STB;
        const int ko = kc * 32;
        const int c  = tid & 3;
        const int r0 = tid >> 2;
        #pragma unroll
        for (int i = 0; i < 2; i++) {
            const int r = r0 + i * 64;
            const uint32_t sw = (uint32_t)(r * 64 + 16 * (c ^ ((r >> 1) & 3)));
            CP16(st + sw,      Ahi + (bm + r) * KDIM + ko + c * 8);
            CP16(st + AB + sw, Bhi + (bn + r) * KDIM + ko + c * 8);
        }
        CP_COMMIT();
    };

    #pragma unroll
    for (int kc = 0; kc < 3; kc++) g2s(kc);

    #pragma unroll 1
    for (int kc = 0; kc < 16; kc++) {
        if (kc <= 13) CP_WAIT_N(2);
        else if (kc == 14) CP_WAIT_N(1);
        else CP_WAIT_N(0);
        __syncthreads();
        if (kc + 3 < 16) g2s(kc + 3);
        const uint32_t st = sb + (uint32_t)(kc & 3) * STB;

        #pragma unroll
        for (int s = 0; s < 2; s++) {
            uint32_t ah[4][4], bh[2][4];
            #pragma unroll
            for (int mf = 0; mf < 4; mf++) {
                const int ar = wm + mf * 16 + (lane & 15);
                const int ac = s * 2 + (lane >> 4);
                LDM_X4(ah[mf], st + (uint32_t)(ar * 64 + 16 * (ac ^ ((ar >> 1) & 3))));
            }
            #pragma unroll
            for (int nf16 = 0; nf16 < 2; nf16++) {
                const int br = wn + nf16 * 16 + (lane & 7) + ((lane >> 4) & 1) * 8;
                const int bc = s * 2 + ((lane >> 3) & 1);
                LDM_X4(bh[nf16], st + AB + (uint32_t)(br * 64 + 16 * (bc ^ ((br >> 1) & 3))));
            }
            #pragma unroll
            for (int mf = 0; mf < 4; mf++)
                #pragma unroll
                for (int nf = 0; nf < 4; nf++)
                    MMA_F16(acc[mf][nf], ah[mf],
                            bh[nf >> 1][(nf & 1) * 2], bh[nf >> 1][(nf & 1) * 2 + 1]);
        }
    }

    // RK4 epilogue
    #pragma unroll
    for (int mf = 0; mf < 4; mf++)
        #pragma unroll
        for (int nf = 0; nf < 4; nf++) {
            const int col = wn + nf * 8 + 2 * (lane & 3);
            const float b0 = bias[bn + col], b1 = bias[bn + col + 1];
            #pragma unroll
            for (int hv = 0; hv < 2; hv++) {
                const size_t row = bm + wm + mf * 16 + (lane >> 2) + 8 * hv;
                const size_t ix = row * 512 + bn + col;
                const float k0 = acc[mf][nf][2 * hv]     + b0;
                const float k1 = acc[mf][nf][2 * hv + 1] + b1;
                if (mode == 0) {
                    *reinterpret_cast<float2*>(Acc + ix) = make_float2(k0, k1);
                    const float2 h2 = *reinterpret_cast<const float2*>(H + ix);
                    *reinterpret_cast<__half2*>(Yhi + ix) =
                        __floats2half2_rn(fmaf(wy, k0, h2.x), fmaf(wy, k1, h2.y));
                } else if (mode == 1) {
                    float2 a2 = *reinterpret_cast<const float2*>(Acc + ix);
                    a2.x = fmaf(wacc, k0, a2.x); a2.y = fmaf(wacc, k1, a2.y);
                    *reinterpret_cast<float2*>(Acc + ix) = a2;
                    const float2 h2 = *reinterpret_cast<const float2*>(H + ix);
                    *reinterpret_cast<__half2*>(Yhi + ix) =
                        __floats2half2_rn(fmaf(wy, k0, h2.x), fmaf(wy, k1, h2.y));
                } else {
                    const float2 a2 = *reinterpret_cast<const float2*>(Acc + ix);
                    float2 h2 = *reinterpret_cast<const float2*>(H + ix);
                    const float cc = 1.0f / 24.0f;
                    h2.x = fmaf(a2.x + k0, cc, h2.x);
                    h2.y = fmaf(a2.y + k1, cc, h2.y);
                    *reinterpret_cast<float2*>(H + ix) = h2;
                    split_store_pair(Yhi, Hlo2, ix, h2.x, h2.y);
                }
            }
        }
}

// ---------------------------------------------------------------------------
// LayerNorm(512)+LeakyReLU, warp-per-row. fp16 in -> fp16 HI only.
// ---------------------------------------------------------------------------
__global__ void ln_lrelu(const __half* __restrict__ Z,
                         const float* __restrict__ g, const float* __restrict__ b,
                         __half* __restrict__ Xhi)
{
    const int lane = threadIdx.x & 31;
    const size_t row = (size_t)blockIdx.x * 8 + (threadIdx.x >> 5);
    const __half* z = Z + row * 512;

    float4 v[4];
    #pragma unroll
    for (int i = 0; i < 4; i++) {
        uint2 raw = *reinterpret_cast<const uint2*>(z + i * 128 + lane * 4);
        const float2 f0 = __half22float2(*reinterpret_cast<__half2*>(&raw.x));
        const float2 f1 = __half22float2(*reinterpret_cast<__half2*>(&raw.y));
        v[i] = make_float4(f0.x, f0.y, f1.x, f1.y);
    }

    float s = 0.f;
    #pragma unroll
    for (int i = 0; i < 4; i++) s += v[i].x + v[i].y + v[i].z + v[i].w;
    #pragma unroll
    for (int o = 16; o > 0; o >>= 1) s += __shfl_xor_sync(0xffffffffu, s, o);
    const float mean = s * (1.0f / 512.0f);

    float q = 0.f;
    #pragma unroll
    for (int i = 0; i < 4; i++) {
        const float d0 = v[i].x - mean, d1 = v[i].y - mean;
        const float d2 = v[i].z - mean, d3 = v[i].w - mean;
        q += d0 * d0 + d1 * d1 + d2 * d2 + d3 * d3;
    }
    #pragma unroll
    for (int o = 16; o > 0; o >>= 1) q += __shfl_xor_sync(0xffffffffu, q, o);
    const float rstd = rsqrtf(q * (1.0f / 512.0f) + 1e-5f);

    #pragma unroll
    for (int i = 0; i < 4; i++) {
        const int c = i * 128 + lane * 4;
        const float4 gg = *reinterpret_cast<const float4*>(g + c);
        const float4 bb = *reinterpret_cast<const float4*>(b + c);
        float y0 = fmaf((v[i].x - mean) * rstd, gg.x, bb.x);
        float y1 = fmaf((v[i].y - mean) * rstd, gg.y, bb.y);
        float y2 = fmaf((v[i].z - mean) * rstd, gg.z, bb.z);
        float y3 = fmaf((v[i].w - mean) * rstd, gg.w, bb.w);
        y0 = (y0 > 0.f) ? y0 : 0.01f * y0;
        y1 = (y1 > 0.f) ? y1 : 0.01f * y1;
        y2 = (y2 > 0.f) ? y2 : 0.01f * y2;
        y3 = (y3 > 0.f) ? y3 : 0.01f * y3;
        *reinterpret_cast<__half2*>(Xhi + row * 512 + c)     = __floats2half2_rn(y0, y1);
        *reinterpret_cast<__half2*>(Xhi + row * 512 + c + 2) = __floats2half2_rn(y2, y3);
    }
}

// ---------------------------------------------------------------------------
// obs -> hidden: Linear(8->512)+LN+LeakyReLU; fp32 H + fp16 split
// ---------------------------------------------------------------------------
__device__ __forceinline__ float block_sum512(float x, float* red, int tid) {
    #pragma unroll
    for (int o = 16; o > 0; o >>= 1) x += __shfl_xor_sync(0xffffffffu, x, o);
    __syncthreads();
    if ((tid & 31) == 0) red[tid >> 5] = x;
    __syncthreads();
    float t = 0.f;
    #pragma unroll
    for (int i = 0; i < 8; i++) t += red[i];
    return t;
}

__global__ void obs_embed(const float* __restrict__ xs, const float* __restrict__ W,
                          const float* __restrict__ bias,
                          const float* __restrict__ lg, const float* __restrict__ lb,
                          float* __restrict__ H,
                          __half* __restrict__ Hhi, __half* __restrict__ Hlo)
{
    __shared__ float xv[8];
    __shared__ float red[8];
    const size_t row = blockIdx.x;
    const int tid = threadIdx.x;
    const int c = 2 * tid;
    if (tid < 8) xv[tid] = xs[row * 8 + tid];
    __syncthreads();
    float2 v = *reinterpret_cast<const float2*>(bias + c);
    #pragma unroll
    for (int k = 0; k < 8; k++) {
        float2 w = *reinterpret_cast<const float2*>(W + k * 512 + c);
        v.x = fmaf(xv[k], w.x, v.x);
        v.y = fmaf(xv[k], w.y, v.y);
    }
    const float mean = block_sum512(v.x + v.y, red, tid) * (1.f / 512.f);
    const float d0 = v.x - mean, d1 = v.y - mean;
    const float rstd = rsqrtf(block_sum512(d0 * d0 + d1 * d1, red, tid) * (1.f / 512.f) + 1e-5f);
    const float2 gg = *reinterpret_cast<const float2*>(lg + c);
    const float2 bb = *reinterpret_cast<const float2*>(lb + c);
    float y0 = fmaf(d0 * rstd, gg.x, bb.x);
    float y1 = fmaf(d1 * rstd, gg.y, bb.y);
    y0 = (y0 > 0.f) ? y0 : 0.01f * y0;
    y1 = (y1 > 0.f) ? y1 : 0.01f * y1;
    *reinterpret_cast<float2*>(H + row * 512 + c) = make_float2(y0, y1);
    split_store_pair(Hhi, Hlo, row * 512 + c, y0, y1);
}

// All 16 time-folded W1 biases at once
__global__ void make_bias_all(float* __restrict__ beff, const float* __restrict__ b1,
                              const float* __restrict__ w1_last)
{
    const int i = blockIdx.x * 256 + threadIdx.x;   // < 16*512
    const int idx = i >> 9;
    const int n = i & 511;
    const int s = idx >> 2, st = idx & 3;
    const float toff[4] = {0.f, 0.125f, 0.125f, 0.25f};
    const float tt = (float)s * 0.25f + toff[st];
    beff[i] = fmaf(tt, w1_last[n], b1[n]);
}

// GRU elementwise (torch gate order r,z,n); fp16 gate inputs, fp32 h + fp16 split
__global__ void gru_step(const __half* __restrict__ GI, const __half* __restrict__ GH,
                         float* __restrict__ Hs,
                         __half* __restrict__ Shi, __half* __restrict__ Slo)
{
    const int i   = blockIdx.x * blockDim.x + threadIdx.x;
    const int row = i >> 9;
    const int n   = i & 511;
    const __half* gi = GI + (size_t)row * 1536;
    const __half* gh = GH + (size_t)row * 1536;
    const float r  = 1.f / (1.f + expf(-(__half2float(gi[n])        + __half2float(gh[n]))));
    const float z  = 1.f / (1.f + expf(-(__half2float(gi[512 + n])  + __half2float(gh[512 + n]))));
    const float nn = tanhf(__half2float(gi[1024 + n]) + r * __half2float(gh[1024 + n]));
    const float h  = (1.f - z) * nn + z * Hs[i];
    Hs[i] = h;
    split1h(h, Shi[i], Slo[i]);
}

// W[K,N] (fp32 row-major) -> Whi/Wlo[N,K] fp16 split (transposed); Wlo optional
__global__ void wsplit(const float* __restrict__ W,
                       __half* __restrict__ Whi, __half* __restrict__ Wlo,
                       int K, int N)
{
    int idx = blockIdx.x * blockDim.x + threadIdx.x;
    if (idx >= K * N) return;
    int k = idx / N, n = idx % N;
    __half hi, lo;
    split1h(W[idx], hi, lo);
    Whi[(size_t)n * K + k] = hi;
    if (Wlo) Wlo[(size_t)n * K + k] = lo;
}

__global__ void zero_state(float* __restrict__ h,
                           __half* __restrict__ hi, __half* __restrict__ lo)
{
    int i = blockIdx.x * blockDim.x + threadIdx.x;
    h[i] = 0.f;
    hi[i] = __float2half(0.f);
    lo[i] = __float2half(0.f);
}

__global__ void copy_kernel(float* __restrict__ dst, const float* __restrict__ src)
{
    int i = blockIdx.x * blockDim.x + threadIdx.x;
    dst[i] = src[i];
}

// ---------------------------------------------------------------------------
// Launch
// ---------------------------------------------------------------------------
extern "C" void kernel_launch(void* const* d_in, const int* in_sizes, int n_in,
                              void* d_out, int out_size)
{
    const float* xs       = (const float*)d_in[0];
    const float* obs_W    = (const float*)d_in[1];
    const float* obs_b    = (const float*)d_in[2];
    const float* obs_lg   = (const float*)d_in[3];
    const float* obs_lb   = (const float*)d_in[4];
    const float* ode_W1   = (const float*)d_in[5];   // [513, 512]
    const float* ode_b1   = (const float*)d_in[6];
    const float* ln1_g    = (const float*)d_in[7];
    const float* ln1_b    = (const float*)d_in[8];
    const float* ode_W2   = (const float*)d_in[9];
    const float* ode_b2   = (const float*)d_in[10];
    const float* ln2_g    = (const float*)d_in[11];
    const float* ln2_b    = (const float*)d_in[12];
    const float* ode_Wout = (const float*)d_in[13];
    const float* ode_bout = (const float*)d_in[14];
    const float* W_ih     = (const float*)d_in[15];  // [512, 1536]
    const float* b_ih     = (const float*)d_in[16];
    const float* W_hh     = (const float*)d_in[17];
    const float* b_hh     = (const float*)d_in[18];

    float *p_h, *p_acc, *p_hst, *p_beff;
    __half *p_zh, *p_gih, *p_ghh;
    __half *p_hhi, *p_hlo, *p_xhi, *p_yhi, *p_shi, *p_slo;
    __half *w1h, *w2h, *woh, *wih, *wil, *whh, *whl;
    cudaGetSymbolAddress((void**)&p_h,    g_h);
    cudaGetSymbolAddress((void**)&p_acc,  g_acc);
    cudaGetSymbolAddress((void**)&p_hst,  g_hst);
    cudaGetSymbolAddress((void**)&p_beff, g_beff);
    cudaGetSymbolAddress((void**)&p_zh,   g_zh);
    cudaGetSymbolAddress((void**)&p_gih,  g_gih);
    cudaGetSymbolAddress((void**)&p_ghh,  g_ghh);
    cudaGetSymbolAddress((void**)&p_hhi,  g_hhi);
    cudaGetSymbolAddress((void**)&p_hlo,  g_hlo);
    cudaGetSymbolAddress((void**)&p_xhi,  g_xhi);
    cudaGetSymbolAddress((void**)&p_yhi,  g_yhi);
    cudaGetSymbolAddress((void**)&p_shi,  g_shi);
    cudaGetSymbolAddress((void**)&p_slo,  g_slo);
    cudaGetSymbolAddress((void**)&w1h,    g_w1hi);
    cudaGetSymbolAddress((void**)&w2h,    g_w2hi);
    cudaGetSymbolAddress((void**)&woh,    g_wohi);
    cudaGetSymbolAddress((void**)&wih,    g_wihi);
    cudaGetSymbolAddress((void**)&wil,    g_wilo);
    cudaGetSymbolAddress((void**)&whh,    g_whhi);
    cudaGetSymbolAddress((void**)&whl,    g_whlo);

    cudaFuncSetAttribute(gemm_f16<128,1,1>, cudaFuncAttributeMaxDynamicSharedMemorySize, SMEM_P1_128);
    cudaFuncSetAttribute(gemm_f16<128,2,1>, cudaFuncAttributeMaxDynamicSharedMemorySize, SMEM_P2_128);
    cudaFuncSetAttribute(gemm_f16<64,2,1>,  cudaFuncAttributeMaxDynamicSharedMemorySize, SMEM_P2_64);
    cudaFuncSetAttribute(gemm_rk4,          cudaFuncAttributeMaxDynamicSharedMemorySize, SMEM_RK4);

    const int M = (int)NROWS;
    __half* nil = nullptr;

    // Weight prep (transpose + fp16 split). W1/W2/Wout need hi only (P1 layers).
    wsplit<<<(512 * 512) / 256, 256>>>(ode_W1,   w1h, nil, 512, 512);
    wsplit<<<(512 * 512) / 256, 256>>>(ode_W2,   w2h, nil, 512, 512);
    wsplit<<<(512 * 512) / 256, 256>>>(ode_Wout, woh, nil, 512, 512);
    wsplit<<<(512 * 1536) / 256, 256>>>(W_ih, wih, wil, 512, 1536);
    wsplit<<<(512 * 1536) / 256, 256>>>(W_hh, whh, whl, 512, 1536);
    make_bias_all<<<32, 256>>>(p_beff, ode_b1, ode_W1 + 512 * 512);

    // obs embedding (ODE initial conditions)
    obs_embed<<<M, 256>>>(xs, obs_W, obs_b, obs_lg, obs_lb, p_h, p_hhi, p_hlo);

    dim3 gBig(512 / 128,  M / 128);       // (4, 512)
    dim3 gGi (1536 / 128, M / 128);       // (12, 512)
    dim3 gGru(1536 / 128, BATCH / 64);    // (12, 16), 2 CTAs/SM -> 1 wave
    const int LNG = M / 8;

    // Batched RK4 over ALL timesteps (effective batch 65536)
    for (int s = 0; s < 4; s++) {
        for (int st = 0; st < 4; st++) {
            const float* beff = p_beff + (size_t)(s * 4 + st) * 512;
            const __half* Ah = (st == 0) ? p_hhi : p_yhi;
            gemm_f16<128,1,1><<<gBig, 256, SMEM_P1_128>>>(Ah, Ah, w1h, w1h, beff, p_zh, 512);
            ln_lrelu<<<LNG, 256>>>(p_zh, ln1_g, ln1_b, p_xhi);
            gemm_f16<128,1,1><<<gBig, 256, SMEM_P1_128>>>(p_xhi, p_xhi, w2h, w2h, ode_b2, p_zh, 512);
            ln_lrelu<<<LNG, 256>>>(p_zh, ln2_g, ln2_b, p_xhi);
            if (st < 3) {
                const float wa = (st == 0) ? 1.f : 2.f;
                const float wy = (st == 2) ? 0.25f : 0.125f;
                gemm_rk4<<<gBig, 256, SMEM_RK4>>>(p_xhi, woh, ode_bout,
                                                  p_h, p_acc, p_yhi, p_hlo,
                                                  wa, wy, (st == 0) ? 0 : 1);
            } else {
                gemm_rk4<<<gBig, 256, SMEM_RK4>>>(p_xhi, woh, ode_bout,
                                                  p_h, p_acc, p_hhi, p_hlo,
                                                  1.f, 0.f, 2);
            }
        }
    }

    // Input gates for all timesteps in one GEMM (P2: state hi x (Whi+Wlo))
    gemm_f16<128,2,1><<<gGi, 256, SMEM_P2_128>>>(p_hhi, p_hhi, wih, wil, b_ih, p_gih, 1536);

    // Sequential GRU (P2 GEMM: state hi x (Whi+Wlo); direct path keeps fp32 h)
    zero_state<<<(BATCH * HID) / 256, 256>>>(p_hst, p_shi, p_slo);
    for (int t = 0; t < T_STEPS; t++) {
        gemm_f16<64,2,1><<<gGru, 256, SMEM_P2_64>>>(p_shi, p_shi, whh, whl, b_hh, p_ghh, 1536);
        gru_step<<<(BATCH * HID) / 256, 256>>>(p_gih + (size_t)t * BATCH * G3, p_ghh,
                                               p_hst, p_shi, p_slo);
    }

    copy_kernel<<<(BATCH * HID) / 256, 256>>>((float*)d_out, p_hst);
}

// round 17
// speedup vs baseline: 2.1273x; 1.0559x over previous
#include <cuda_runtime.h>
#include <cuda_fp16.h>
#include <cstdint>
#include <cstddef>

// ---------------------------------------------------------------------------
// Dims
// ---------------------------------------------------------------------------
constexpr int    T_STEPS = 64;
constexpr int    BATCH   = 1024;
constexpr int    HID     = 512;
constexpr int    G3      = 3 * HID;                  // 1536
constexpr size_t NROWS   = (size_t)T_STEPS * BATCH;  // 65536
constexpr int    KDIM    = 512;

// ---------------------------------------------------------------------------
// PTX helpers (arch-unconditional, sm_80-era)
// ---------------------------------------------------------------------------
__device__ __forceinline__ uint32_t smem_u32(const void* p) {
    uint32_t a;
    asm("{ .reg .u64 t; cvta.to.shared.u64 t, %1; cvt.u32.u64 %0, t; }"
        : "=r"(a) : "l"(p));
    return a;
}
#define CP16(s, g) \
    asm volatile("cp.async.cg.shared.global [%0], [%1], 16;\n" :: "r"(s), "l"(g) : "memory")
#define CP_COMMIT() asm volatile("cp.async.commit_group;\n" ::: "memory")
#define CP_WAIT_N(n) asm volatile("cp.async.wait_group %0;" :: "n"(n) : "memory")

#define LDM_X4(r, addr)                                                         \
    asm volatile("ldmatrix.sync.aligned.m8n8.x4.shared.b16 {%0,%1,%2,%3}, [%4];" \
        : "=r"((r)[0]), "=r"((r)[1]), "=r"((r)[2]), "=r"((r)[3]) : "r"(addr))

#define MMA_F16(d, a, b0, b1)                                                   \
    asm volatile("mma.sync.aligned.m16n8k16.row.col.f32.f16.f16.f32 "           \
        "{%0,%1,%2,%3}, {%4,%5,%6,%7}, {%8,%9}, {%0,%1,%2,%3};"                 \
        : "+f"((d)[0]), "+f"((d)[1]), "+f"((d)[2]), "+f"((d)[3])                \
        : "r"((a)[0]), "r"((a)[1]), "r"((a)[2]), "r"((a)[3]), "r"(b0), "r"(b1))

// ---------------------------------------------------------------------------
// Scratch
// ---------------------------------------------------------------------------
__device__ float g_h   [NROWS * HID];     // fp32 ODE state
__device__ float g_acc [NROWS * HID];     // RK4 accumulator
__device__ float g_hst [BATCH * HID];
__device__ float g_beff[16 * HID];        // all 16 time-folded W1 biases

__device__ __half g_zh [NROWS * HID];     // fp16 GEMM out (pre-LN)
__device__ __half g_gih[NROWS * G3];      // fp16 input gates
__device__ __half g_ghh[BATCH * G3];      // fp16 hidden gates

__device__ __half g_hhi[NROWS * HID], g_hlo[NROWS * HID];  // h state split
__device__ __half g_xhi[NROWS * HID];                      // LN outputs (hi only)
__device__ __half g_yhi[NROWS * HID];                      // RK4 Y output (hi only)
__device__ __half g_shi[BATCH * HID], g_slo[BATCH * HID];  // GRU state split
__device__ __half g_w1hi[HID * HID];
__device__ __half g_w2hi[HID * HID];
__device__ __half g_wohi[HID * HID];
__device__ __half g_wihi[G3 * HID];
__device__ __half g_whhi[G3 * HID];

// ---------------------------------------------------------------------------
// fp16 split helpers
// ---------------------------------------------------------------------------
__device__ __forceinline__ void split1h(float v, __half& hi, __half& lo) {
    hi = __float2half(v);
    lo = __float2half(v - __half2float(hi));
}
__device__ __forceinline__ void split_store_pair(__half* Hi, __half* Lo,
                                                 size_t i, float a, float b) {
    __half2 h, l;
    split1h(a, h.x, l.x); split1h(b, h.y, l.y);
    *reinterpret_cast<__half2*>(Hi + i) = h;
    *reinterpret_cast<__half2*>(Lo + i) = l;
}

// ===========================================================================
// fp16 split GEMM: C[M,N] = A @ B^T + bias, B pre-transposed [N,512].
// PRODUCTS==1: C = Ah*Bh.  PRODUCTS==2: + Ah*Bl.  PRODUCTS==3: + Al*Bh.
// OUTH==1: fp16 output.  Stages: P1=6, P2=4, P3=3.
// BM x 128 tile, BK=32, 16 chunks, 256 threads (8 warps 2Mx4N).
// ===========================================================================
template<int BM, int PRODUCTS, int OUTH>
__global__ void __launch_bounds__(256, (PRODUCTS <= 2 || BM == 64) ? 2 : 1)
gemm_f16(const __half* __restrict__ Ahi, const __half* __restrict__ Alo,
         const __half* __restrict__ Bhi, const __half* __restrict__ Blo,
         const float* __restrict__ bias, void* __restrict__ Cv, int N)
{
    constexpr int MF    = BM / 32;
    constexpr int AB    = BM * 64;
    constexpr int ASETS = (PRODUCTS == 3) ? 2 : 1;
    constexpr int BSETS = (PRODUCTS >= 2) ? 2 : 1;
    constexpr int STB   = ASETS * AB + BSETS * 8192;
    constexpr int S     = (PRODUCTS == 3) ? 3 : ((PRODUCTS == 1) ? 6 : 4);

    extern __shared__ char smem[];
    const uint32_t sb = smem_u32(smem);
    const int tid  = threadIdx.x;
    const int lane = tid & 31;
    const int wid  = tid >> 5;
    const int wm   = (wid >> 2) * (BM / 2);
    const int wn   = (wid & 3) * 32;
    const size_t bm = (size_t)blockIdx.y * BM;
    const size_t bn = (size_t)blockIdx.x * 128;

    float acc[MF][4][4];
    #pragma unroll
    for (int i = 0; i < MF; i++)
        #pragma unroll
        for (int j = 0; j < 4; j++)
            #pragma unroll
            for (int v = 0; v < 4; v++) acc[i][j][v] = 0.f;

    auto g2s = [&](int kc) {
        const uint32_t st = sb + (uint32_t)(kc % S) * STB;
        const int ko = kc * 32;
        const int c  = tid & 3;
        const int r0 = tid >> 2;
        #pragma unroll
        for (int i = 0; i < BM / 64; i++) {
            const int r = r0 + i * 64;
            const uint32_t sw = (uint32_t)(r * 64 + 16 * (c ^ ((r >> 1) & 3)));
            CP16(st + sw, Ahi + (bm + r) * KDIM + ko + c * 8);
            if constexpr (PRODUCTS == 3)
                CP16(st + AB + sw, Alo + (bm + r) * KDIM + ko + c * 8);
        }
        #pragma unroll
        for (int i = 0; i < 2; i++) {
            const int r = r0 + i * 64;
            const uint32_t sw = (uint32_t)(r * 64 + 16 * (c ^ ((r >> 1) & 3)));
            CP16(st + ASETS * AB + sw, Bhi + (bn + r) * KDIM + ko + c * 8);
            if constexpr (PRODUCTS >= 2)
                CP16(st + ASETS * AB + 8192 + sw, Blo + (bn + r) * KDIM + ko + c * 8);
        }
        CP_COMMIT();
    };

    #pragma unroll
    for (int kc = 0; kc < S - 1; kc++) g2s(kc);

    #pragma unroll 1
    for (int kc = 0; kc < 16; kc++) {
        // group kc must be complete after this wait
        if (kc <= 16 - (S - 1)) CP_WAIT_N(S - 2);
        else if (kc == 12)      CP_WAIT_N(3);
        else if (kc == 13)      CP_WAIT_N(2);
        else if (kc == 14)      CP_WAIT_N(1);
        else                    CP_WAIT_N(0);
        __syncthreads();
        if (kc + S - 1 < 16) g2s(kc + S - 1);
        const uint32_t st = sb + (uint32_t)(kc % S) * STB;

        #pragma unroll
        for (int s = 0; s < 2; s++) {
            uint32_t ah[MF][4], al[MF][4], bh[2][4], bl[2][4];
            #pragma unroll
            for (int mf = 0; mf < MF; mf++) {
                const int ar = wm + mf * 16 + (lane & 15);
                const int ac = s * 2 + (lane >> 4);
                const uint32_t sw = (uint32_t)(ar * 64 + 16 * (ac ^ ((ar >> 1) & 3)));
                LDM_X4(ah[mf], st + sw);
                if constexpr (PRODUCTS == 3) LDM_X4(al[mf], st + AB + sw);
            }
            #pragma unroll
            for (int nf16 = 0; nf16 < 2; nf16++) {
                const int br = wn + nf16 * 16 + (lane & 7) + ((lane >> 4) & 1) * 8;
                const int bc = s * 2 + ((lane >> 3) & 1);
                const uint32_t sw = (uint32_t)(br * 64 + 16 * (bc ^ ((br >> 1) & 3)));
                LDM_X4(bh[nf16], st + ASETS * AB + sw);
                if constexpr (PRODUCTS >= 2)
                    LDM_X4(bl[nf16], st + ASETS * AB + 8192 + sw);
            }
            #pragma unroll
            for (int mf = 0; mf < MF; mf++)
                #pragma unroll
                for (int nf = 0; nf < 4; nf++) {
                    const uint32_t b0h = bh[nf >> 1][(nf & 1) * 2];
                    const uint32_t b1h = bh[nf >> 1][(nf & 1) * 2 + 1];
                    MMA_F16(acc[mf][nf], ah[mf], b0h, b1h);
                    if constexpr (PRODUCTS >= 2)
                        MMA_F16(acc[mf][nf], ah[mf],
                                bl[nf >> 1][(nf & 1) * 2], bl[nf >> 1][(nf & 1) * 2 + 1]);
                    if constexpr (PRODUCTS == 3)
                        MMA_F16(acc[mf][nf], al[mf], b0h, b1h);
                }
        }
    }

    #pragma unroll
    for (int mf = 0; mf < MF; mf++) {
        const size_t r0 = bm + wm + mf * 16 + (lane >> 2);
        #pragma unroll
        for (int nf = 0; nf < 4; nf++) {
            const int col = wn + nf * 8 + (lane & 3) * 2;
            const float b0 = bias[bn + col], b1 = bias[bn + col + 1];
            if constexpr (OUTH) {
                __half* Ch = reinterpret_cast<__half*>(Cv);
                *reinterpret_cast<__half2*>(Ch + r0 * N + bn + col) =
                    __floats2half2_rn(acc[mf][nf][0] + b0, acc[mf][nf][1] + b1);
                *reinterpret_cast<__half2*>(Ch + (r0 + 8) * N + bn + col) =
                    __floats2half2_rn(acc[mf][nf][2] + b0, acc[mf][nf][3] + b1);
            } else {
                float* C = reinterpret_cast<float*>(Cv);
                *reinterpret_cast<float2*>(C + r0 * N + bn + col) =
                    make_float2(acc[mf][nf][0] + b0, acc[mf][nf][1] + b1);
                *reinterpret_cast<float2*>(C + (r0 + 8) * N + bn + col) =
                    make_float2(acc[mf][nf][2] + b0, acc[mf][nf][3] + b1);
            }
        }
    }
}

constexpr int SMEM_P1_128 = 6 * (128 * 64 + 8192);        // 98304 (S=6)
constexpr int SMEM_P1_64  = 6 * (64 * 64 + 8192);         // 73728 (S=6)
constexpr int SMEM_RK4    = 4 * (128 * 64 + 8192);        // 65536 (P1, S=4)

// ===========================================================================
// Wout GEMM (P1: Ah*Bh only, BM=128, N=512) + RK4 epilogue.
// mode0: Acc=K, Y=H+wy*K -> Yhi.  mode1: Acc+=wacc*K, Y -> Yhi.
// mode2: H+=(Acc+K)/24 -> H fp32, Yhi=hi(H), Hlo2=lo(H).
// ===========================================================================
__global__ void __launch_bounds__(256, 2)
gemm_rk4(const __half* __restrict__ Ahi,
         const __half* __restrict__ Bhi,
         const float* __restrict__ bias,
         float* __restrict__ H, float* __restrict__ Acc,
         __half* __restrict__ Yhi, __half* __restrict__ Hlo2,
         float wacc, float wy, int mode)
{
    constexpr int AB  = 128 * 64;
    constexpr int STB = AB + 8192;      // 16384
    extern __shared__ char smem[];
    const uint32_t sb = smem_u32(smem);
    const int tid  = threadIdx.x;
    const int lane = tid & 31;
    const int wid  = tid >> 5;
    const int wm   = (wid >> 2) * 64;
    const int wn   = (wid & 3) * 32;
    const size_t bm = (size_t)blockIdx.y * 128;
    const size_t bn = (size_t)blockIdx.x * 128;

    float acc[4][4][4];
    #pragma unroll
    for (int i = 0; i < 4; i++)
        #pragma unroll
        for (int j = 0; j < 4; j++)
            #pragma unroll
            for (int v = 0; v < 4; v++) acc[i][j][v] = 0.f;

    auto g2s = [&](int kc) {
        const uint32_t st = sb + (uint32_t)(kc & 3) * STB;
        const int ko = kc * 32;
        const int c  = tid & 3;
        const int r0 = tid >> 2;
        #pragma unroll
        for (int i = 0; i < 2; i++) {
            const int r = r0 + i * 64;
            const uint32_t sw = (uint32_t)(r * 64 + 16 * (c ^ ((r >> 1) & 3)));
            CP16(st + sw,      Ahi + (bm + r) * KDIM + ko + c * 8);
            CP16(st + AB + sw, Bhi + (bn + r) * KDIM + ko + c * 8);
        }
        CP_COMMIT();
    };

    #pragma unroll
    for (int kc = 0; kc < 3; kc++) g2s(kc);

    #pragma unroll 1
    for (int kc = 0; kc < 16; kc++) {
        if (kc <= 13) CP_WAIT_N(2);
        else if (kc == 14) CP_WAIT_N(1);
        else CP_WAIT_N(0);
        __syncthreads();
        if (kc + 3 < 16) g2s(kc + 3);
        const uint32_t st = sb + (uint32_t)(kc & 3) * STB;

        #pragma unroll
        for (int s = 0; s < 2; s++) {
            uint32_t ah[4][4], bh[2][4];
            #pragma unroll
            for (int mf = 0; mf < 4; mf++) {
                const int ar = wm + mf * 16 + (lane & 15);
                const int ac = s * 2 + (lane >> 4);
                LDM_X4(ah[mf], st + (uint32_t)(ar * 64 + 16 * (ac ^ ((ar >> 1) & 3))));
            }
            #pragma unroll
            for (int nf16 = 0; nf16 < 2; nf16++) {
                const int br = wn + nf16 * 16 + (lane & 7) + ((lane >> 4) & 1) * 8;
                const int bc = s * 2 + ((lane >> 3) & 1);
                LDM_X4(bh[nf16], st + AB + (uint32_t)(br * 64 + 16 * (bc ^ ((br >> 1) & 3))));
            }
            #pragma unroll
            for (int mf = 0; mf < 4; mf++)
                #pragma unroll
                for (int nf = 0; nf < 4; nf++)
                    MMA_F16(acc[mf][nf], ah[mf],
                            bh[nf >> 1][(nf & 1) * 2], bh[nf >> 1][(nf & 1) * 2 + 1]);
        }
    }

    // RK4 epilogue
    #pragma unroll
    for (int mf = 0; mf < 4; mf++)
        #pragma unroll
        for (int nf = 0; nf < 4; nf++) {
            const int col = wn + nf * 8 + 2 * (lane & 3);
            const float b0 = bias[bn + col], b1 = bias[bn + col + 1];
            #pragma unroll
            for (int hv = 0; hv < 2; hv++) {
                const size_t row = bm + wm + mf * 16 + (lane >> 2) + 8 * hv;
                const size_t ix = row * 512 + bn + col;
                const float k0 = acc[mf][nf][2 * hv]     + b0;
                const float k1 = acc[mf][nf][2 * hv + 1] + b1;
                if (mode == 0) {
                    *reinterpret_cast<float2*>(Acc + ix) = make_float2(k0, k1);
                    const float2 h2 = *reinterpret_cast<const float2*>(H + ix);
                    *reinterpret_cast<__half2*>(Yhi + ix) =
                        __floats2half2_rn(fmaf(wy, k0, h2.x), fmaf(wy, k1, h2.y));
                } else if (mode == 1) {
                    float2 a2 = *reinterpret_cast<const float2*>(Acc + ix);
                    a2.x = fmaf(wacc, k0, a2.x); a2.y = fmaf(wacc, k1, a2.y);
                    *reinterpret_cast<float2*>(Acc + ix) = a2;
                    const float2 h2 = *reinterpret_cast<const float2*>(H + ix);
                    *reinterpret_cast<__half2*>(Yhi + ix) =
                        __floats2half2_rn(fmaf(wy, k0, h2.x), fmaf(wy, k1, h2.y));
                } else {
                    const float2 a2 = *reinterpret_cast<const float2*>(Acc + ix);
                    float2 h2 = *reinterpret_cast<const float2*>(H + ix);
                    const float cc = 1.0f / 24.0f;
                    h2.x = fmaf(a2.x + k0, cc, h2.x);
                    h2.y = fmaf(a2.y + k1, cc, h2.y);
                    *reinterpret_cast<float2*>(H + ix) = h2;
                    split_store_pair(Yhi, Hlo2, ix, h2.x, h2.y);
                }
            }
        }
}

// ---------------------------------------------------------------------------
// LayerNorm(512)+LeakyReLU, warp-per-row. fp16 in -> fp16 HI only.
// ---------------------------------------------------------------------------
__global__ void ln_lrelu(const __half* __restrict__ Z,
                         const float* __restrict__ g, const float* __restrict__ b,
                         __half* __restrict__ Xhi)
{
    const int lane = threadIdx.x & 31;
    const size_t row = (size_t)blockIdx.x * 8 + (threadIdx.x >> 5);
    const __half* z = Z + row * 512;

    float4 v[4];
    #pragma unroll
    for (int i = 0; i < 4; i++) {
        uint2 raw = *reinterpret_cast<const uint2*>(z + i * 128 + lane * 4);
        const float2 f0 = __half22float2(*reinterpret_cast<__half2*>(&raw.x));
        const float2 f1 = __half22float2(*reinterpret_cast<__half2*>(&raw.y));
        v[i] = make_float4(f0.x, f0.y, f1.x, f1.y);
    }

    float s = 0.f;
    #pragma unroll
    for (int i = 0; i < 4; i++) s += v[i].x + v[i].y + v[i].z + v[i].w;
    #pragma unroll
    for (int o = 16; o > 0; o >>= 1) s += __shfl_xor_sync(0xffffffffu, s, o);
    const float mean = s * (1.0f / 512.0f);

    float q = 0.f;
    #pragma unroll
    for (int i = 0; i < 4; i++) {
        const float d0 = v[i].x - mean, d1 = v[i].y - mean;
        const float d2 = v[i].z - mean, d3 = v[i].w - mean;
        q += d0 * d0 + d1 * d1 + d2 * d2 + d3 * d3;
    }
    #pragma unroll
    for (int o = 16; o > 0; o >>= 1) q += __shfl_xor_sync(0xffffffffu, q, o);
    const float rstd = rsqrtf(q * (1.0f / 512.0f) + 1e-5f);

    #pragma unroll
    for (int i = 0; i < 4; i++) {
        const int c = i * 128 + lane * 4;
        const float4 gg = *reinterpret_cast<const float4*>(g + c);
        const float4 bb = *reinterpret_cast<const float4*>(b + c);
        float y0 = fmaf((v[i].x - mean) * rstd, gg.x, bb.x);
        float y1 = fmaf((v[i].y - mean) * rstd, gg.y, bb.y);
        float y2 = fmaf((v[i].z - mean) * rstd, gg.z, bb.z);
        float y3 = fmaf((v[i].w - mean) * rstd, gg.w, bb.w);
        y0 = (y0 > 0.f) ? y0 : 0.01f * y0;
        y1 = (y1 > 0.f) ? y1 : 0.01f * y1;
        y2 = (y2 > 0.f) ? y2 : 0.01f * y2;
        y3 = (y3 > 0.f) ? y3 : 0.01f * y3;
        *reinterpret_cast<__half2*>(Xhi + row * 512 + c)     = __floats2half2_rn(y0, y1);
        *reinterpret_cast<__half2*>(Xhi + row * 512 + c + 2) = __floats2half2_rn(y2, y3);
    }
}

// ---------------------------------------------------------------------------
// obs -> hidden: Linear(8->512)+LN+LeakyReLU; fp32 H + fp16 split
// ---------------------------------------------------------------------------
__device__ __forceinline__ float block_sum512(float x, float* red, int tid) {
    #pragma unroll
    for (int o = 16; o > 0; o >>= 1) x += __shfl_xor_sync(0xffffffffu, x, o);
    __syncthreads();
    if ((tid & 31) == 0) red[tid >> 5] = x;
    __syncthreads();
    float t = 0.f;
    #pragma unroll
    for (int i = 0; i < 8; i++) t += red[i];
    return t;
}

__global__ void obs_embed(const float* __restrict__ xs, const float* __restrict__ W,
                          const float* __restrict__ bias,
                          const float* __restrict__ lg, const float* __restrict__ lb,
                          float* __restrict__ H,
                          __half* __restrict__ Hhi, __half* __restrict__ Hlo)
{
    __shared__ float xv[8];
    __shared__ float red[8];
    const size_t row = blockIdx.x;
    const int tid = threadIdx.x;
    const int c = 2 * tid;
    if (tid < 8) xv[tid] = xs[row * 8 + tid];
    __syncthreads();
    float2 v = *reinterpret_cast<const float2*>(bias + c);
    #pragma unroll
    for (int k = 0; k < 8; k++) {
        float2 w = *reinterpret_cast<const float2*>(W + k * 512 + c);
        v.x = fmaf(xv[k], w.x, v.x);
        v.y = fmaf(xv[k], w.y, v.y);
    }
    const float mean = block_sum512(v.x + v.y, red, tid) * (1.f / 512.f);
    const float d0 = v.x - mean, d1 = v.y - mean;
    const float rstd = rsqrtf(block_sum512(d0 * d0 + d1 * d1, red, tid) * (1.f / 512.f) + 1e-5f);
    const float2 gg = *reinterpret_cast<const float2*>(lg + c);
    const float2 bb = *reinterpret_cast<const float2*>(lb + c);
    float y0 = fmaf(d0 * rstd, gg.x, bb.x);
    float y1 = fmaf(d1 * rstd, gg.y, bb.y);
    y0 = (y0 > 0.f) ? y0 : 0.01f * y0;
    y1 = (y1 > 0.f) ? y1 : 0.01f * y1;
    *reinterpret_cast<float2*>(H + row * 512 + c) = make_float2(y0, y1);
    split_store_pair(Hhi, Hlo, row * 512 + c, y0, y1);
}

// All 16 time-folded W1 biases at once
__global__ void make_bias_all(float* __restrict__ beff, const float* __restrict__ b1,
                              const float* __restrict__ w1_last)
{
    const int i = blockIdx.x * 256 + threadIdx.x;   // < 16*512
    const int idx = i >> 9;
    const int n = i & 511;
    const int s = idx >> 2, st = idx & 3;
    const float toff[4] = {0.f, 0.125f, 0.125f, 0.25f};
    const float tt = (float)s * 0.25f + toff[st];
    beff[i] = fmaf(tt, w1_last[n], b1[n]);
}

// GRU elementwise (torch gate order r,z,n); fp16 gate inputs, fp32 h + fp16 split
__global__ void gru_step(const __half* __restrict__ GI, const __half* __restrict__ GH,
                         float* __restrict__ Hs,
                         __half* __restrict__ Shi, __half* __restrict__ Slo)
{
    const int i   = blockIdx.x * blockDim.x + threadIdx.x;
    const int row = i >> 9;
    const int n   = i & 511;
    const __half* gi = GI + (size_t)row * 1536;
    const __half* gh = GH + (size_t)row * 1536;
    const float r  = 1.f / (1.f + expf(-(__half2float(gi[n])        + __half2float(gh[n]))));
    const float z  = 1.f / (1.f + expf(-(__half2float(gi[512 + n])  + __half2float(gh[512 + n]))));
    const float nn = tanhf(__half2float(gi[1024 + n]) + r * __half2float(gh[1024 + n]));
    const float h  = (1.f - z) * nn + z * Hs[i];
    Hs[i] = h;
    split1h(h, Shi[i], Slo[i]);
}

// W[K,N] (fp32 row-major) -> Whi/Wlo[N,K] fp16 split (transposed); Wlo optional
__global__ void wsplit(const float* __restrict__ W,
                       __half* __restrict__ Whi, __half* __restrict__ Wlo,
                       int K, int N)
{
    int idx = blockIdx.x * blockDim.x + threadIdx.x;
    if (idx >= K * N) return;
    int k = idx / N, n = idx % N;
    __half hi, lo;
    split1h(W[idx], hi, lo);
    Whi[(size_t)n * K + k] = hi;
    if (Wlo) Wlo[(size_t)n * K + k] = lo;
}

__global__ void zero_state(float* __restrict__ h,
                           __half* __restrict__ hi, __half* __restrict__ lo)
{
    int i = blockIdx.x * blockDim.x + threadIdx.x;
    h[i] = 0.f;
    hi[i] = __float2half(0.f);
    lo[i] = __float2half(0.f);
}

__global__ void copy_kernel(float* __restrict__ dst, const float* __restrict__ src)
{
    int i = blockIdx.x * blockDim.x + threadIdx.x;
    dst[i] = src[i];
}

// ---------------------------------------------------------------------------
// Launch
// ---------------------------------------------------------------------------
extern "C" void kernel_launch(void* const* d_in, const int* in_sizes, int n_in,
                              void* d_out, int out_size)
{
    const float* xs       = (const float*)d_in[0];
    const float* obs_W    = (const float*)d_in[1];
    const float* obs_b    = (const float*)d_in[2];
    const float* obs_lg   = (const float*)d_in[3];
    const float* obs_lb   = (const float*)d_in[4];
    const float* ode_W1   = (const float*)d_in[5];   // [513, 512]
    const float* ode_b1   = (const float*)d_in[6];
    const float* ln1_g    = (const float*)d_in[7];
    const float* ln1_b    = (const float*)d_in[8];
    const float* ode_W2   = (const float*)d_in[9];
    const float* ode_b2   = (const float*)d_in[10];
    const float* ln2_g    = (const float*)d_in[11];
    const float* ln2_b    = (const float*)d_in[12];
    const float* ode_Wout = (const float*)d_in[13];
    const float* ode_bout = (const float*)d_in[14];
    const float* W_ih     = (const float*)d_in[15];  // [512, 1536]
    const float* b_ih     = (const float*)d_in[16];
    const float* W_hh     = (const float*)d_in[17];
    const float* b_hh     = (const float*)d_in[18];

    float *p_h, *p_acc, *p_hst, *p_beff;
    __half *p_zh, *p_gih, *p_ghh;
    __half *p_hhi, *p_hlo, *p_xhi, *p_yhi, *p_shi, *p_slo;
    __half *w1h, *w2h, *woh, *wih, *whh;
    cudaGetSymbolAddress((void**)&p_h,    g_h);
    cudaGetSymbolAddress((void**)&p_acc,  g_acc);
    cudaGetSymbolAddress((void**)&p_hst,  g_hst);
    cudaGetSymbolAddress((void**)&p_beff, g_beff);
    cudaGetSymbolAddress((void**)&p_zh,   g_zh);
    cudaGetSymbolAddress((void**)&p_gih,  g_gih);
    cudaGetSymbolAddress((void**)&p_ghh,  g_ghh);
    cudaGetSymbolAddress((void**)&p_hhi,  g_hhi);
    cudaGetSymbolAddress((void**)&p_hlo,  g_hlo);
    cudaGetSymbolAddress((void**)&p_xhi,  g_xhi);
    cudaGetSymbolAddress((void**)&p_yhi,  g_yhi);
    cudaGetSymbolAddress((void**)&p_shi,  g_shi);
    cudaGetSymbolAddress((void**)&p_slo,  g_slo);
    cudaGetSymbolAddress((void**)&w1h,    g_w1hi);
    cudaGetSymbolAddress((void**)&w2h,    g_w2hi);
    cudaGetSymbolAddress((void**)&woh,    g_wohi);
    cudaGetSymbolAddress((void**)&wih,    g_wihi);
    cudaGetSymbolAddress((void**)&whh,    g_whhi);

    cudaFuncSetAttribute(gemm_f16<128,1,1>, cudaFuncAttributeMaxDynamicSharedMemorySize, SMEM_P1_128);
    cudaFuncSetAttribute(gemm_f16<64,1,1>,  cudaFuncAttributeMaxDynamicSharedMemorySize, SMEM_P1_64);
    cudaFuncSetAttribute(gemm_rk4,          cudaFuncAttributeMaxDynamicSharedMemorySize, SMEM_RK4);

    const int M = (int)NROWS;
    __half* nil = nullptr;

    // Weight prep (transpose + fp16 hi only — all GEMMs are P1 now).
    wsplit<<<(512 * 512) / 256, 256>>>(ode_W1,   w1h, nil, 512, 512);
    wsplit<<<(512 * 512) / 256, 256>>>(ode_W2,   w2h, nil, 512, 512);
    wsplit<<<(512 * 512) / 256, 256>>>(ode_Wout, woh, nil, 512, 512);
    wsplit<<<(512 * 1536) / 256, 256>>>(W_ih, wih, nil, 512, 1536);
    wsplit<<<(512 * 1536) / 256, 256>>>(W_hh, whh, nil, 512, 1536);
    make_bias_all<<<32, 256>>>(p_beff, ode_b1, ode_W1 + 512 * 512);

    // obs embedding (ODE initial conditions)
    obs_embed<<<M, 256>>>(xs, obs_W, obs_b, obs_lg, obs_lb, p_h, p_hhi, p_hlo);

    dim3 gBig(512 / 128,  M / 128);       // (4, 512)
    dim3 gGi (1536 / 128, M / 128);       // (12, 512)
    dim3 gGru(1536 / 128, BATCH / 64);    // (12, 16), 2 CTAs/SM -> 1 wave
    const int LNG = M / 8;

    // Batched RK4 over ALL timesteps (effective batch 65536)
    for (int s = 0; s < 4; s++) {
        for (int st = 0; st < 4; st++) {
            const float* beff = p_beff + (size_t)(s * 4 + st) * 512;
            const __half* Ah = (st == 0) ? p_hhi : p_yhi;
            gemm_f16<128,1,1><<<gBig, 256, SMEM_P1_128>>>(Ah, Ah, w1h, w1h, beff, p_zh, 512);
            ln_lrelu<<<LNG, 256>>>(p_zh, ln1_g, ln1_b, p_xhi);
            gemm_f16<128,1,1><<<gBig, 256, SMEM_P1_128>>>(p_xhi, p_xhi, w2h, w2h, ode_b2, p_zh, 512);
            ln_lrelu<<<LNG, 256>>>(p_zh, ln2_g, ln2_b, p_xhi);
            if (st < 3) {
                const float wa = (st == 0) ? 1.f : 2.f;
                const float wy = (st == 2) ? 0.25f : 0.125f;
                gemm_rk4<<<gBig, 256, SMEM_RK4>>>(p_xhi, woh, ode_bout,
                                                  p_h, p_acc, p_yhi, p_hlo,
                                                  wa, wy, (st == 0) ? 0 : 1);
            } else {
                gemm_rk4<<<gBig, 256, SMEM_RK4>>>(p_xhi, woh, ode_bout,
                                                  p_h, p_acc, p_hhi, p_hlo,
                                                  1.f, 0.f, 2);
            }
        }
    }

    // Input gates for all timesteps in one GEMM (P1: state hi x Whi)
    gemm_f16<128,1,1><<<gGi, 256, SMEM_P1_128>>>(p_hhi, p_hhi, wih, wih, b_ih, p_gih, 1536);

    // Sequential GRU (P1 GEMM: state hi x Whh-hi; direct path keeps fp32 h)
    zero_state<<<(BATCH * HID) / 256, 256>>>(p_hst, p_shi, p_slo);
    for (int t = 0; t < T_STEPS; t++) {
        gemm_f16<64,1,1><<<gGru, 256, SMEM_P1_64>>>(p_shi, p_shi, whh, whh, b_hh, p_ghh, 1536);
        gru_step<<<(BATCH * HID) / 256, 256>>>(p_gih + (size_t)t * BATCH * G3, p_ghh,
                                               p_hst, p_shi, p_slo);
    }

    copy_kernel<<<(BATCH * HID) / 256, 256>>>((float*)d_out, p_hst);
}